// round 7
// baseline (speedup 1.0000x reference)
#include <cuda_runtime.h>
#include <cuda_bf16.h>
#include <math.h>
#include <stdint.h>

#define N 256
#define NT (N*N)
#define C 128
#define H 4
#define D 32

// -------- scratch (device globals; no allocation allowed) --------
__device__ float    g_lnz[NT*C];
__device__ float    g_q[NT*C];
__device__ float    g_k[NT*C];
__device__ float    g_v[NT*C];
__device__ float    g_g[NT*C];     // sigmoid(z@Wg)
__device__ float    g_bt[H*NT];    // bias transposed: [h][k][j]
__device__ float    g_o[NT*C];     // gated attention output
__device__ uint32_t g_wph[5*C*(C/2)];
__device__ uint32_t g_wpl[5*C*(C/2)];

struct Y4 { float* p[4]; };
struct W5 { const float* w[5]; };

// ---------- helpers ----------
__device__ __forceinline__ float bf16val(float x) {
    return __bfloat162float(__float2bfloat16(x));
}
__device__ __forceinline__ uint32_t bf16pair(float even, float odd) {
    uint32_t r;
    asm("cvt.rn.satfinite.bf16x2.f32 %0, %1, %2;" : "=r"(r) : "f"(odd), "f"(even));
    return r;
}
__device__ __forceinline__ void mma_bf16(float* c, const uint32_t* a,
                                         const uint32_t* b) {
    asm volatile(
        "mma.sync.aligned.m16n8k16.row.col.f32.bf16.bf16.f32 "
        "{%0,%1,%2,%3},{%4,%5,%6,%7},{%8,%9},{%0,%1,%2,%3};"
        : "+f"(c[0]), "+f"(c[1]), "+f"(c[2]), "+f"(c[3])
        : "r"(a[0]), "r"(a[1]), "r"(a[2]), "r"(a[3]), "r"(b[0]), "r"(b[1]));
}
__device__ __forceinline__ uint32_t to_tf32(float x) {
    uint32_t u;
    asm("cvt.rna.tf32.f32 %0, %1;" : "=r"(u) : "f"(x));
    return u;
}
__device__ __forceinline__ void mma_tf32(float* c, const uint32_t* a,
                                         const uint32_t* b) {
    asm volatile(
        "mma.sync.aligned.m16n8k8.row.col.f32.tf32.tf32.f32 "
        "{%0,%1,%2,%3},{%4,%5,%6,%7},{%8,%9},{%0,%1,%2,%3};"
        : "+f"(c[0]), "+f"(c[1]), "+f"(c[2]), "+f"(c[3])
        : "r"(a[0]), "r"(a[1]), "r"(a[2]), "r"(a[3]), "r"(b[0]), "r"(b[1]));
}
__device__ __forceinline__ void cp16(uint32_t* smem_dst, const void* gsrc) {
    uint32_t s = (uint32_t)__cvta_generic_to_shared(smem_dst);
    asm volatile("cp.async.cg.shared.global [%0], [%1], 16;\n"
                 :: "r"(s), "l"(gsrc));
}

// ---------------- LayerNorm + fused bias projection ----------------
__global__ void ln_kernel(const float* __restrict__ z,
                          const float* __restrict__ gamma,
                          const float* __restrict__ beta,
                          const float* __restrict__ Wb) {
    int warp = threadIdx.x >> 5, lane = threadIdx.x & 31;
    int t = blockIdx.x * 8 + warp;
    const float4 v = *(const float4*)(z + (size_t)t * C + lane * 4);
    float s = v.x + v.y + v.z + v.w;
    #pragma unroll
    for (int o = 16; o; o >>= 1) s += __shfl_xor_sync(0xffffffffu, s, o);
    float mu = s * (1.0f / C);
    float d0 = v.x - mu, d1 = v.y - mu, d2 = v.z - mu, d3 = v.w - mu;
    float vs = d0*d0 + d1*d1 + d2*d2 + d3*d3;
    #pragma unroll
    for (int o = 16; o; o >>= 1) vs += __shfl_xor_sync(0xffffffffu, vs, o);
    float r = rsqrtf(vs * (1.0f / C) + 1e-5f);
    float4 gm = *(const float4*)(gamma + lane * 4);
    float4 bt = *(const float4*)(beta + lane * 4);
    float4 out;
    out.x = d0 * r * gm.x + bt.x;
    out.y = d1 * r * gm.y + bt.y;
    out.z = d2 * r * gm.z + bt.z;
    out.w = d3 * r * gm.w + bt.w;
    *(float4*)(g_lnz + (size_t)t * C + lane * 4) = out;

    // fused bias = lnz @ Wb (4 heads), warp reduce
    float4 w0 = *(const float4*)(Wb + lane * 16);
    float4 w1 = *(const float4*)(Wb + lane * 16 + 4);
    float4 w2 = *(const float4*)(Wb + lane * 16 + 8);
    float4 w3 = *(const float4*)(Wb + lane * 16 + 12);
    float4 p;
    p.x = out.x * w0.x + out.y * w1.x + out.z * w2.x + out.w * w3.x;
    p.y = out.x * w0.y + out.y * w1.y + out.z * w2.y + out.w * w3.y;
    p.z = out.x * w0.z + out.y * w1.z + out.z * w2.z + out.w * w3.z;
    p.w = out.x * w0.w + out.y * w1.w + out.z * w2.w + out.w * w3.w;
    #pragma unroll
    for (int o = 16; o; o >>= 1) {
        p.x += __shfl_xor_sync(0xffffffffu, p.x, o);
        p.y += __shfl_xor_sync(0xffffffffu, p.y, o);
        p.z += __shfl_xor_sync(0xffffffffu, p.z, o);
        p.w += __shfl_xor_sync(0xffffffffu, p.w, o);
    }
    if (lane == 0) {
        int j = t >> 8, k = t & 255;
        g_bt[((size_t)0 * N + k) * N + j] = p.x;
        g_bt[((size_t)1 * N + k) * N + j] = p.y;
        g_bt[((size_t)2 * N + k) * N + j] = p.z;
        g_bt[((size_t)3 * N + k) * N + j] = p.w;
    }
}

// ------- weight prep: split + pack + transpose -------
__global__ void wprep_kernel(W5 ws) {
    int mat = blockIdx.y;
    int idx = blockIdx.x * 256 + threadIdx.x;
    int n = idx >> 6, k2 = idx & 63;
    const float* W = ws.w[mat];
    float w0 = W[(2 * k2) * C + n];
    float w1 = W[(2 * k2 + 1) * C + n];
    float h0 = bf16val(w0), h1 = bf16val(w1);
    g_wph[mat * 8192 + n * 64 + k2] = bf16pair(w0, w1);
    g_wpl[mat * 8192 + n * 64 + k2] = bf16pair(w0 - h0, w1 - h1);
}

// ---------------- fused bf16-3x GEMM (unchanged from R6) ----------------
#define XW 68
#define XPLANE (128 * XW)
#define WBUF (2 * XPLANE)
#define GEMM_SMEM ((2 * XPLANE + 2 * WBUF) * 4)

__global__ void __launch_bounds__(256, 1)
gemm_fused(const float* __restrict__ X, int slot0, int nmat, Y4 ys, int sigmask) {
    extern __shared__ uint32_t sm4[];
    uint32_t* Xh2 = sm4;
    uint32_t* Xl2 = sm4 + XPLANE;
    uint32_t* Wb  = sm4 + 2 * XPLANE;

    int tid = threadIdx.x;
    int warp = tid >> 5, lane = tid & 31;
    int g = lane >> 2, t = lane & 3;
    int wm = warp >> 1, wn = warp & 1;
    int row0 = blockIdx.x * 128;

    auto issueW = [&](int s, int buf) {
        uint32_t* wb = Wb + buf * WBUF;
        #pragma unroll
        for (int i = 0; i < 16; i++) {
            int id = tid + i * 256;
            int plane = id >> 11, r = id & 2047;
            int n = r >> 4, q = r & 15;
            const uint32_t* src =
                (plane ? g_wpl : g_wph) + (slot0 + s) * 8192 + n * 64 + q * 4;
            cp16(wb + plane * XPLANE + n * XW + q * 4, src);
        }
    };

    issueW(0, 0);
    asm volatile("cp.async.commit_group;\n");
    #pragma unroll
    for (int i = 0; i < 16; i++) {
        int id = tid + i * 256;
        int row = id >> 5, c4 = id & 31;
        float4 v = *(const float4*)(X + (size_t)(row0 + row) * C + c4 * 4);
        float h0 = bf16val(v.x), h1 = bf16val(v.y);
        float h2 = bf16val(v.z), h3 = bf16val(v.w);
        uint32_t* xh = Xh2 + row * XW + c4 * 2;
        uint32_t* xl = Xl2 + row * XW + c4 * 2;
        xh[0] = bf16pair(v.x, v.y);
        xh[1] = bf16pair(v.z, v.w);
        xl[0] = bf16pair(v.x - h0, v.y - h1);
        xl[1] = bf16pair(v.z - h2, v.w - h3);
    }

    #pragma unroll 1
    for (int s = 0; s < nmat; s++) {
        if (s + 1 < nmat) {
            issueW(s + 1, (s + 1) & 1);
            asm volatile("cp.async.commit_group;\n");
            asm volatile("cp.async.wait_group 1;\n");
        } else {
            asm volatile("cp.async.wait_group 0;\n");
        }
        __syncthreads();

        uint32_t* Wh2 = Wb + (s & 1) * WBUF;
        uint32_t* Wl2 = Wh2 + XPLANE;

        float c[2][8][4];
        #pragma unroll
        for (int mb = 0; mb < 2; mb++)
            #pragma unroll
            for (int nb = 0; nb < 8; nb++)
                #pragma unroll
                for (int r = 0; r < 4; r++) c[mb][nb][r] = 0.0f;

        #pragma unroll
        for (int ks = 0; ks < 8; ks++) {
            int kb = ks * 8;
            uint32_t bh[8][2], bl[8][2];
            #pragma unroll
            for (int nb = 0; nb < 8; nb++) {
                int n = wn * 64 + nb * 8 + g;
                bh[nb][0] = Wh2[n * XW + kb + t];
                bh[nb][1] = Wh2[n * XW + kb + t + 4];
                bl[nb][0] = Wl2[n * XW + kb + t];
                bl[nb][1] = Wl2[n * XW + kb + t + 4];
            }
            #pragma unroll
            for (int mb = 0; mb < 2; mb++) {
                int r = wm * 32 + mb * 16 + g;
                uint32_t ah[4], al[4];
                ah[0] = Xh2[r * XW + kb + t];
                ah[1] = Xh2[(r + 8) * XW + kb + t];
                ah[2] = Xh2[r * XW + kb + t + 4];
                ah[3] = Xh2[(r + 8) * XW + kb + t + 4];
                al[0] = Xl2[r * XW + kb + t];
                al[1] = Xl2[(r + 8) * XW + kb + t];
                al[2] = Xl2[r * XW + kb + t + 4];
                al[3] = Xl2[(r + 8) * XW + kb + t + 4];
                #pragma unroll
                for (int nb = 0; nb < 8; nb++) {
                    mma_bf16(c[mb][nb], ah, bh[nb]);
                    mma_bf16(c[mb][nb], ah, bl[nb]);
                    mma_bf16(c[mb][nb], al, bh[nb]);
                }
            }
        }

        float* Y = ys.p[s];
        int sg = (sigmask >> s) & 1;
        #pragma unroll
        for (int mb = 0; mb < 2; mb++) {
            int r0 = row0 + wm * 32 + mb * 16 + g;
            #pragma unroll
            for (int nb = 0; nb < 8; nb++) {
                int col = wn * 64 + nb * 8 + 2 * t;
                float v0 = c[mb][nb][0], v1 = c[mb][nb][1];
                float v2 = c[mb][nb][2], v3 = c[mb][nb][3];
                if (sg) {
                    v0 = 1.0f / (1.0f + __expf(-v0));
                    v1 = 1.0f / (1.0f + __expf(-v1));
                    v2 = 1.0f / (1.0f + __expf(-v2));
                    v3 = 1.0f / (1.0f + __expf(-v3));
                }
                *(float2*)(Y + (size_t)r0 * C + col) = make_float2(v0, v1);
                *(float2*)(Y + (size_t)(r0 + 8) * C + col) = make_float2(v2, v3);
            }
        }
        __syncthreads();
    }
}

// ---------------- attention: 2 i-values per block ----------------
// QK^T: bf16-3x (K packed pairs in smem). PV: tf32. Bias reused across i via L1.
#define KP 20     // K pair-row stride (words): banks 20g+t all distinct
#define VP 40     // V row stride: banks 8t+g all distinct
#define PST 36
#define KPL (256 * KP)            // 5120 words per plane per i
#define VPL (256 * VP)            // 10240 words per i
#define ATTN_SMEM ((4 * KPL + 2 * VPL + 8 * 32 * PST) * 4)  // 200704 B

__global__ void __launch_bounds__(256)
attn_mma() {
    extern __shared__ uint32_t smu[];
    uint32_t* Kh = smu;                    // [ii][256][KP]
    uint32_t* Kl = smu + 2 * KPL;
    float* Vs = (float*)(smu + 4 * KPL);   // [ii][256][VP]
    float* Ps = (float*)(smu + 4 * KPL + 2 * VPL);

    int i0 = blockIdx.x * 2, h = blockIdx.y;
    int tid = threadIdx.x;
    int w = tid >> 5, lane = tid & 31;
    int g = lane >> 2, t = lane & 3;
    int coff = h * D;
    float* Pw = Ps + w * 32 * PST;
    const float sc = 0.17677669529663687f;

    // --- stage K (bf16 hi/lo pairs) and V (tf32) for both i ---
    #pragma unroll
    for (int it = 0; it < 16; it++) {
        int idx = tid + it * 256;
        int ii = idx >> 11, r = idx & 2047;
        int tok = r >> 3, f = r & 7;
        size_t gbase = (size_t)(i0 + ii) * N;
        float4 kv = *(const float4*)(g_k + (gbase + tok) * C + coff + f * 4);
        float h0 = bf16val(kv.x), h1 = bf16val(kv.y);
        float h2 = bf16val(kv.z), h3 = bf16val(kv.w);
        uint32_t* kh = Kh + ii * KPL + tok * KP + f * 2;
        uint32_t* kl = Kl + ii * KPL + tok * KP + f * 2;
        kh[0] = bf16pair(kv.x, kv.y);
        kh[1] = bf16pair(kv.z, kv.w);
        kl[0] = bf16pair(kv.x - h0, kv.y - h1);
        kl[1] = bf16pair(kv.z - h2, kv.w - h3);
        float4 vv = *(const float4*)(g_v + (gbase + tok) * C + coff + f * 4);
        float4 vt;
        vt.x = __uint_as_float(to_tf32(vv.x));
        vt.y = __uint_as_float(to_tf32(vv.y));
        vt.z = __uint_as_float(to_tf32(vv.z));
        vt.w = __uint_as_float(to_tf32(vv.w));
        *(float4*)(Vs + ii * VPL + tok * VP + f * 4) = vt;
    }

    // --- Q (scaled) registers, bf16 hi/lo pairs, both i ---
    int jb = w * 32;
    uint32_t qh[2][2][2][4], ql[2][2][2][4];   // [ii][mb][ks][4]
    #pragma unroll
    for (int ii = 0; ii < 2; ii++) {
        size_t gbase = (size_t)(i0 + ii) * N;
        #pragma unroll
        for (int mb = 0; mb < 2; mb++) {
            int j1 = jb + mb * 16 + g, j2 = j1 + 8;
            #pragma unroll
            for (int ks = 0; ks < 2; ks++) {
                int d0 = 2 * (ks * 8 + t), d1 = 2 * (ks * 8 + t + 4);
                float2 qa = *(const float2*)(g_q + (gbase + j1) * C + coff + d0);
                float2 qb = *(const float2*)(g_q + (gbase + j2) * C + coff + d0);
                float2 qc = *(const float2*)(g_q + (gbase + j1) * C + coff + d1);
                float2 qd = *(const float2*)(g_q + (gbase + j2) * C + coff + d1);
                qa.x *= sc; qa.y *= sc; qb.x *= sc; qb.y *= sc;
                qc.x *= sc; qc.y *= sc; qd.x *= sc; qd.y *= sc;
                float a0 = bf16val(qa.x), a1 = bf16val(qa.y);
                float b0 = bf16val(qb.x), b1 = bf16val(qb.y);
                float c0 = bf16val(qc.x), c1 = bf16val(qc.y);
                float e0 = bf16val(qd.x), e1 = bf16val(qd.y);
                qh[ii][mb][ks][0] = bf16pair(qa.x, qa.y);
                qh[ii][mb][ks][1] = bf16pair(qb.x, qb.y);
                qh[ii][mb][ks][2] = bf16pair(qc.x, qc.y);
                qh[ii][mb][ks][3] = bf16pair(qd.x, qd.y);
                ql[ii][mb][ks][0] = bf16pair(qa.x - a0, qa.y - a1);
                ql[ii][mb][ks][1] = bf16pair(qb.x - b0, qb.y - b1);
                ql[ii][mb][ks][2] = bf16pair(qc.x - c0, qc.y - c1);
                ql[ii][mb][ks][3] = bf16pair(qd.x - e0, qd.y - e1);
            }
        }
    }
    __syncthreads();

    float o[2][2][4][4];
    #pragma unroll
    for (int ii = 0; ii < 2; ii++)
        #pragma unroll
        for (int mb = 0; mb < 2; mb++)
            #pragma unroll
            for (int nb = 0; nb < 4; nb++)
                #pragma unroll
                for (int r = 0; r < 4; r++) o[ii][mb][nb][r] = 0.0f;
    float lsum[2][2][2];
    #pragma unroll
    for (int ii = 0; ii < 2; ii++)
        #pragma unroll
        for (int mb = 0; mb < 2; mb++) { lsum[ii][mb][0] = 0.f; lsum[ii][mb][1] = 0.f; }

    const float* bth = g_bt + (size_t)h * NT;

    for (int ch = 0; ch < 8; ch++) {
        int tok0 = ch * 32;
        #pragma unroll 1
        for (int ii = 0; ii < 2; ii++) {
            // ---- S = Q K^T (bf16-3x) ----
            float s[2][4][4];
            #pragma unroll
            for (int mb = 0; mb < 2; mb++)
                #pragma unroll
                for (int nt = 0; nt < 4; nt++)
                    #pragma unroll
                    for (int r = 0; r < 4; r++) s[mb][nt][r] = 0.0f;
            #pragma unroll
            for (int nt = 0; nt < 4; nt++) {
                int tokn = tok0 + nt * 8 + g;
                #pragma unroll
                for (int ks = 0; ks < 2; ks++) {
                    uint32_t bh2[2], bl2[2];
                    const uint32_t* kh = Kh + ii * KPL + tokn * KP + ks * 8;
                    const uint32_t* kl = Kl + ii * KPL + tokn * KP + ks * 8;
                    bh2[0] = kh[t]; bh2[1] = kh[t + 4];
                    bl2[0] = kl[t]; bl2[1] = kl[t + 4];
                    #pragma unroll
                    for (int mb = 0; mb < 2; mb++) {
                        mma_bf16(s[mb][nt], qh[ii][mb][ks], bh2);
                        mma_bf16(s[mb][nt], qh[ii][mb][ks], bl2);
                        mma_bf16(s[mb][nt], ql[ii][mb][ks], bh2);
                    }
                }
            }
            // ---- bias + exp + P ----
            #pragma unroll
            for (int mb = 0; mb < 2; mb++) {
                int j1 = jb + mb * 16 + g, j2 = j1 + 8;
                #pragma unroll
                for (int nt = 0; nt < 4; nt++) {
                    int k0 = tok0 + nt * 8 + 2 * t;
                    float b00 = bth[(size_t)k0 * N + j1];
                    float b01 = bth[(size_t)(k0 + 1) * N + j1];
                    float b10 = bth[(size_t)k0 * N + j2];
                    float b11 = bth[(size_t)(k0 + 1) * N + j2];
                    float p0 = __expf(s[mb][nt][0] + b00);
                    float p1 = __expf(s[mb][nt][1] + b01);
                    float p2 = __expf(s[mb][nt][2] + b10);
                    float p3 = __expf(s[mb][nt][3] + b11);
                    lsum[ii][mb][0] += p0 + p1;
                    lsum[ii][mb][1] += p2 + p3;
                    int cc = nt * 8 + 2 * t;
                    Pw[(mb*16 + g) * PST + cc]     = __uint_as_float(to_tf32(p0));
                    Pw[(mb*16 + g) * PST + cc + 1] = __uint_as_float(to_tf32(p1));
                    Pw[(mb*16 + 8 + g) * PST + cc]     = __uint_as_float(to_tf32(p2));
                    Pw[(mb*16 + 8 + g) * PST + cc + 1] = __uint_as_float(to_tf32(p3));
                }
            }
            __syncwarp();
            // ---- O += P V ----
            #pragma unroll
            for (int ks = 0; ks < 4; ks++) {
                uint32_t pa[2][4];
                #pragma unroll
                for (int mb = 0; mb < 2; mb++) {
                    pa[mb][0] = __float_as_uint(Pw[(mb*16 + g) * PST + ks*8 + t]);
                    pa[mb][1] = __float_as_uint(Pw[(mb*16 + 8 + g) * PST + ks*8 + t]);
                    pa[mb][2] = __float_as_uint(Pw[(mb*16 + g) * PST + ks*8 + t + 4]);
                    pa[mb][3] = __float_as_uint(Pw[(mb*16 + 8 + g) * PST + ks*8 + t + 4]);
                }
                #pragma unroll
                for (int nb = 0; nb < 4; nb++) {
                    uint32_t vb[2];
                    const float* vp = Vs + ii * VPL + (tok0 + ks*8) * VP + nb*8 + g;
                    vb[0] = __float_as_uint(vp[t * VP]);
                    vb[1] = __float_as_uint(vp[(t + 4) * VP]);
                    #pragma unroll
                    for (int mb = 0; mb < 2; mb++)
                        mma_tf32(o[ii][mb][nb], pa[mb], vb);
                }
            }
            __syncwarp();
        }
    }

    // ---- normalize, gate, store ----
    #pragma unroll
    for (int ii = 0; ii < 2; ii++) {
        size_t gbase = (size_t)(i0 + ii) * N;
        #pragma unroll
        for (int mb = 0; mb < 2; mb++) {
            float la = lsum[ii][mb][0], lb = lsum[ii][mb][1];
            la += __shfl_xor_sync(0xffffffffu, la, 1);
            la += __shfl_xor_sync(0xffffffffu, la, 2);
            lb += __shfl_xor_sync(0xffffffffu, lb, 1);
            lb += __shfl_xor_sync(0xffffffffu, lb, 2);
            float inv1 = 1.0f / la, inv2 = 1.0f / lb;
            int j1 = jb + mb * 16 + g, j2 = j1 + 8;
            #pragma unroll
            for (int nb = 0; nb < 4; nb++) {
                int d = nb * 8 + 2 * t;
                float2 g1 = *(const float2*)(g_g + (gbase + j1) * C + coff + d);
                float2 g2 = *(const float2*)(g_g + (gbase + j2) * C + coff + d);
                float2 o1, o2;
                o1.x = g1.x * o[ii][mb][nb][0] * inv1;
                o1.y = g1.y * o[ii][mb][nb][1] * inv1;
                o2.x = g2.x * o[ii][mb][nb][2] * inv2;
                o2.y = g2.y * o[ii][mb][nb][3] * inv2;
                *(float2*)(g_o + (gbase + j1) * C + coff + d) = o1;
                *(float2*)(g_o + (gbase + j2) * C + coff + d) = o2;
            }
        }
    }
}

extern "C" void kernel_launch(void* const* d_in, const int* in_sizes, int n_in,
                              void* d_out, int out_size) {
    const float* z     = (const float*)d_in[0];
    const float* gamma = (const float*)d_in[1];
    const float* beta  = (const float*)d_in[2];
    const float* Wq    = (const float*)d_in[3];
    const float* Wk    = (const float*)d_in[4];
    const float* Wv    = (const float*)d_in[5];
    const float* Wb    = (const float*)d_in[6];
    const float* Wg    = (const float*)d_in[7];
    const float* Wout  = (const float*)d_in[8];
    float* out = (float*)d_out;

    void *p_lnz, *p_q, *p_k, *p_v, *p_g, *p_o;
    cudaGetSymbolAddress(&p_lnz, g_lnz);
    cudaGetSymbolAddress(&p_q, g_q);
    cudaGetSymbolAddress(&p_k, g_k);
    cudaGetSymbolAddress(&p_v, g_v);
    cudaGetSymbolAddress(&p_g, g_g);
    cudaGetSymbolAddress(&p_o, g_o);

    cudaFuncSetAttribute(gemm_fused,
                         cudaFuncAttributeMaxDynamicSharedMemorySize, GEMM_SMEM);
    cudaFuncSetAttribute(attn_mma,
                         cudaFuncAttributeMaxDynamicSharedMemorySize, ATTN_SMEM);

    ln_kernel<<<NT / 8, 256>>>(z, gamma, beta, Wb);
    W5 ws; ws.w[0] = Wq; ws.w[1] = Wk; ws.w[2] = Wv; ws.w[3] = Wg; ws.w[4] = Wout;
    wprep_kernel<<<dim3(32, 5), 256>>>(ws);

    Y4 yq; yq.p[0] = (float*)p_q; yq.p[1] = (float*)p_k;
    yq.p[2] = (float*)p_v; yq.p[3] = (float*)p_g;
    gemm_fused<<<NT / 128, 256, GEMM_SMEM>>>((const float*)p_lnz, 0, 4, yq, 0x8);

    attn_mma<<<dim3(N / 2, H), 256, ATTN_SMEM>>>();

    Y4 yo; yo.p[0] = out; yo.p[1] = yo.p[2] = yo.p[3] = nullptr;
    gemm_fused<<<NT / 128, 256, GEMM_SMEM>>>((const float*)p_o, 4, 1, yo, 0);
}

// round 8
// speedup vs baseline: 1.2362x; 1.2362x over previous
#include <cuda_runtime.h>
#include <cuda_bf16.h>
#include <math.h>
#include <stdint.h>

#define N 256
#define NT (N*N)
#define C 128
#define H 4
#define D 32

// -------- scratch (device globals; no allocation allowed) --------
__device__ float    g_lnz[NT*C];
__device__ float    g_q[NT*C];
__device__ float    g_k[NT*C];
__device__ float    g_v[NT*C];
__device__ float    g_g[NT*C];     // sigmoid(z@Wg)
__device__ float    g_bt[H*NT];    // bias transposed: [h][k][j]
__device__ float    g_o[NT*C];     // gated attention output
__device__ uint32_t g_wph[5*C*(C/2)];
__device__ uint32_t g_wpl[5*C*(C/2)];

struct Y4 { float* p[4]; };
struct W5 { const float* w[5]; };

// ---------- helpers ----------
__device__ __forceinline__ float bf16val(float x) {
    return __bfloat162float(__float2bfloat16(x));
}
__device__ __forceinline__ uint32_t bf16pair(float even, float odd) {
    uint32_t r;
    asm("cvt.rn.satfinite.bf16x2.f32 %0, %1, %2;" : "=r"(r) : "f"(odd), "f"(even));
    return r;
}
__device__ __forceinline__ void mma_bf16(float* c, const uint32_t* a,
                                         const uint32_t* b) {
    asm volatile(
        "mma.sync.aligned.m16n8k16.row.col.f32.bf16.bf16.f32 "
        "{%0,%1,%2,%3},{%4,%5,%6,%7},{%8,%9},{%0,%1,%2,%3};"
        : "+f"(c[0]), "+f"(c[1]), "+f"(c[2]), "+f"(c[3])
        : "r"(a[0]), "r"(a[1]), "r"(a[2]), "r"(a[3]), "r"(b[0]), "r"(b[1]));
}
__device__ __forceinline__ uint32_t to_tf32(float x) {
    uint32_t u;
    asm("cvt.rna.tf32.f32 %0, %1;" : "=r"(u) : "f"(x));
    return u;
}
__device__ __forceinline__ void mma_tf32(float* c, const uint32_t* a,
                                         const uint32_t* b) {
    asm volatile(
        "mma.sync.aligned.m16n8k8.row.col.f32.tf32.tf32.f32 "
        "{%0,%1,%2,%3},{%4,%5,%6,%7},{%8,%9},{%0,%1,%2,%3};"
        : "+f"(c[0]), "+f"(c[1]), "+f"(c[2]), "+f"(c[3])
        : "r"(a[0]), "r"(a[1]), "r"(a[2]), "r"(a[3]), "r"(b[0]), "r"(b[1]));
}
__device__ __forceinline__ void cp16(uint32_t* smem_dst, const void* gsrc) {
    uint32_t s = (uint32_t)__cvta_generic_to_shared(smem_dst);
    asm volatile("cp.async.cg.shared.global [%0], [%1], 16;\n"
                 :: "r"(s), "l"(gsrc));
}

// ---------------- LayerNorm + fused bias projection ----------------
__global__ void ln_kernel(const float* __restrict__ z,
                          const float* __restrict__ gamma,
                          const float* __restrict__ beta,
                          const float* __restrict__ Wb) {
    int warp = threadIdx.x >> 5, lane = threadIdx.x & 31;
    int t = blockIdx.x * 8 + warp;
    const float4 v = *(const float4*)(z + (size_t)t * C + lane * 4);
    float s = v.x + v.y + v.z + v.w;
    #pragma unroll
    for (int o = 16; o; o >>= 1) s += __shfl_xor_sync(0xffffffffu, s, o);
    float mu = s * (1.0f / C);
    float d0 = v.x - mu, d1 = v.y - mu, d2 = v.z - mu, d3 = v.w - mu;
    float vs = d0*d0 + d1*d1 + d2*d2 + d3*d3;
    #pragma unroll
    for (int o = 16; o; o >>= 1) vs += __shfl_xor_sync(0xffffffffu, vs, o);
    float r = rsqrtf(vs * (1.0f / C) + 1e-5f);
    float4 gm = *(const float4*)(gamma + lane * 4);
    float4 bt = *(const float4*)(beta + lane * 4);
    float4 out;
    out.x = d0 * r * gm.x + bt.x;
    out.y = d1 * r * gm.y + bt.y;
    out.z = d2 * r * gm.z + bt.z;
    out.w = d3 * r * gm.w + bt.w;
    *(float4*)(g_lnz + (size_t)t * C + lane * 4) = out;

    float4 w0 = *(const float4*)(Wb + lane * 16);
    float4 w1 = *(const float4*)(Wb + lane * 16 + 4);
    float4 w2 = *(const float4*)(Wb + lane * 16 + 8);
    float4 w3 = *(const float4*)(Wb + lane * 16 + 12);
    float4 p;
    p.x = out.x * w0.x + out.y * w1.x + out.z * w2.x + out.w * w3.x;
    p.y = out.x * w0.y + out.y * w1.y + out.z * w2.y + out.w * w3.y;
    p.z = out.x * w0.z + out.y * w1.z + out.z * w2.z + out.w * w3.z;
    p.w = out.x * w0.w + out.y * w1.w + out.z * w2.w + out.w * w3.w;
    #pragma unroll
    for (int o = 16; o; o >>= 1) {
        p.x += __shfl_xor_sync(0xffffffffu, p.x, o);
        p.y += __shfl_xor_sync(0xffffffffu, p.y, o);
        p.z += __shfl_xor_sync(0xffffffffu, p.z, o);
        p.w += __shfl_xor_sync(0xffffffffu, p.w, o);
    }
    if (lane == 0) {
        int j = t >> 8, k = t & 255;
        g_bt[((size_t)0 * N + k) * N + j] = p.x;
        g_bt[((size_t)1 * N + k) * N + j] = p.y;
        g_bt[((size_t)2 * N + k) * N + j] = p.z;
        g_bt[((size_t)3 * N + k) * N + j] = p.w;
    }
}

// ------- weight prep: split + pack + transpose -------
__global__ void wprep_kernel(W5 ws) {
    int mat = blockIdx.y;
    int idx = blockIdx.x * 256 + threadIdx.x;
    int n = idx >> 6, k2 = idx & 63;
    const float* W = ws.w[mat];
    float w0 = W[(2 * k2) * C + n];
    float w1 = W[(2 * k2 + 1) * C + n];
    float h0 = bf16val(w0), h1 = bf16val(w1);
    g_wph[mat * 8192 + n * 64 + k2] = bf16pair(w0, w1);
    g_wpl[mat * 8192 + n * 64 + k2] = bf16pair(w0 - h0, w1 - h1);
}

// ---------------- fused bf16-3x GEMM (unchanged) ----------------
#define XW 68
#define XPLANE (128 * XW)
#define WBUF (2 * XPLANE)
#define GEMM_SMEM ((2 * XPLANE + 2 * WBUF) * 4)

__global__ void __launch_bounds__(256, 1)
gemm_fused(const float* __restrict__ X, int slot0, int nmat, Y4 ys, int sigmask) {
    extern __shared__ uint32_t sm4[];
    uint32_t* Xh2 = sm4;
    uint32_t* Xl2 = sm4 + XPLANE;
    uint32_t* Wb  = sm4 + 2 * XPLANE;

    int tid = threadIdx.x;
    int warp = tid >> 5, lane = tid & 31;
    int g = lane >> 2, t = lane & 3;
    int wm = warp >> 1, wn = warp & 1;
    int row0 = blockIdx.x * 128;

    auto issueW = [&](int s, int buf) {
        uint32_t* wb = Wb + buf * WBUF;
        #pragma unroll
        for (int i = 0; i < 16; i++) {
            int id = tid + i * 256;
            int plane = id >> 11, r = id & 2047;
            int n = r >> 4, q = r & 15;
            const uint32_t* src =
                (plane ? g_wpl : g_wph) + (slot0 + s) * 8192 + n * 64 + q * 4;
            cp16(wb + plane * XPLANE + n * XW + q * 4, src);
        }
    };

    issueW(0, 0);
    asm volatile("cp.async.commit_group;\n");
    #pragma unroll
    for (int i = 0; i < 16; i++) {
        int id = tid + i * 256;
        int row = id >> 5, c4 = id & 31;
        float4 v = *(const float4*)(X + (size_t)(row0 + row) * C + c4 * 4);
        float h0 = bf16val(v.x), h1 = bf16val(v.y);
        float h2 = bf16val(v.z), h3 = bf16val(v.w);
        uint32_t* xh = Xh2 + row * XW + c4 * 2;
        uint32_t* xl = Xl2 + row * XW + c4 * 2;
        xh[0] = bf16pair(v.x, v.y);
        xh[1] = bf16pair(v.z, v.w);
        xl[0] = bf16pair(v.x - h0, v.y - h1);
        xl[1] = bf16pair(v.z - h2, v.w - h3);
    }

    #pragma unroll 1
    for (int s = 0; s < nmat; s++) {
        if (s + 1 < nmat) {
            issueW(s + 1, (s + 1) & 1);
            asm volatile("cp.async.commit_group;\n");
            asm volatile("cp.async.wait_group 1;\n");
        } else {
            asm volatile("cp.async.wait_group 0;\n");
        }
        __syncthreads();

        uint32_t* Wh2 = Wb + (s & 1) * WBUF;
        uint32_t* Wl2 = Wh2 + XPLANE;

        float c[2][8][4];
        #pragma unroll
        for (int mb = 0; mb < 2; mb++)
            #pragma unroll
            for (int nb = 0; nb < 8; nb++)
                #pragma unroll
                for (int r = 0; r < 4; r++) c[mb][nb][r] = 0.0f;

        #pragma unroll
        for (int ks = 0; ks < 8; ks++) {
            int kb = ks * 8;
            uint32_t bh[8][2], bl[8][2];
            #pragma unroll
            for (int nb = 0; nb < 8; nb++) {
                int n = wn * 64 + nb * 8 + g;
                bh[nb][0] = Wh2[n * XW + kb + t];
                bh[nb][1] = Wh2[n * XW + kb + t + 4];
                bl[nb][0] = Wl2[n * XW + kb + t];
                bl[nb][1] = Wl2[n * XW + kb + t + 4];
            }
            #pragma unroll
            for (int mb = 0; mb < 2; mb++) {
                int r = wm * 32 + mb * 16 + g;
                uint32_t ah[4], al[4];
                ah[0] = Xh2[r * XW + kb + t];
                ah[1] = Xh2[(r + 8) * XW + kb + t];
                ah[2] = Xh2[r * XW + kb + t + 4];
                ah[3] = Xh2[(r + 8) * XW + kb + t + 4];
                al[0] = Xl2[r * XW + kb + t];
                al[1] = Xl2[(r + 8) * XW + kb + t];
                al[2] = Xl2[r * XW + kb + t + 4];
                al[3] = Xl2[(r + 8) * XW + kb + t + 4];
                #pragma unroll
                for (int nb = 0; nb < 8; nb++) {
                    mma_bf16(c[mb][nb], ah, bh[nb]);
                    mma_bf16(c[mb][nb], ah, bl[nb]);
                    mma_bf16(c[mb][nb], al, bh[nb]);
                }
            }
        }

        float* Y = ys.p[s];
        int sg = (sigmask >> s) & 1;
        #pragma unroll
        for (int mb = 0; mb < 2; mb++) {
            int r0 = row0 + wm * 32 + mb * 16 + g;
            #pragma unroll
            for (int nb = 0; nb < 8; nb++) {
                int col = wn * 64 + nb * 8 + 2 * t;
                float v0 = c[mb][nb][0], v1 = c[mb][nb][1];
                float v2 = c[mb][nb][2], v3 = c[mb][nb][3];
                if (sg) {
                    v0 = 1.0f / (1.0f + __expf(-v0));
                    v1 = 1.0f / (1.0f + __expf(-v1));
                    v2 = 1.0f / (1.0f + __expf(-v2));
                    v3 = 1.0f / (1.0f + __expf(-v3));
                }
                *(float2*)(Y + (size_t)r0 * C + col) = make_float2(v0, v1);
                *(float2*)(Y + (size_t)(r0 + 8) * C + col) = make_float2(v2, v3);
            }
        }
        __syncthreads();
    }
}

// ---------------- attention: 1 i per block, bf16-3x QK^T, tf32 PV ----------------
#define KP 20     // K pair-row stride (words): banks (20g+t) distinct
#define VP 40     // V row stride: banks (8t+g) distinct
#define PST 36
#define KPL (256 * KP)
#define VPL (256 * VP)
#define ATTN_SMEM ((2 * KPL + VPL + 8 * 32 * PST) * 4)   // 118784 B

__global__ void __launch_bounds__(256)
attn_mma() {
    extern __shared__ uint32_t smu[];
    uint32_t* Kh = smu;                    // [256][KP] bf16 pairs
    uint32_t* Kl = smu + KPL;
    float* Vs = (float*)(smu + 2 * KPL);   // [256][VP] tf32
    float* Ps = (float*)(smu + 2 * KPL + VPL);

    int i = blockIdx.x, h = blockIdx.y;
    int tid = threadIdx.x;
    int w = tid >> 5, lane = tid & 31;
    int g = lane >> 2, t = lane & 3;
    int coff = h * D;
    size_t gbase = (size_t)i * N;
    float* Pw = Ps + w * 32 * PST;
    const float sc = 0.17677669529663687f;

    // --- stage K (bf16 hi/lo pairs) and V (tf32) ---
    #pragma unroll
    for (int it = 0; it < 8; it++) {
        int idx = tid + it * 256;
        int tok = idx >> 3, f = idx & 7;
        float4 kv = *(const float4*)(g_k + (gbase + tok) * C + coff + f * 4);
        float h0 = bf16val(kv.x), h1 = bf16val(kv.y);
        float h2 = bf16val(kv.z), h3 = bf16val(kv.w);
        uint32_t* kh = Kh + tok * KP + f * 2;
        uint32_t* kl = Kl + tok * KP + f * 2;
        kh[0] = bf16pair(kv.x, kv.y);
        kh[1] = bf16pair(kv.z, kv.w);
        kl[0] = bf16pair(kv.x - h0, kv.y - h1);
        kl[1] = bf16pair(kv.z - h2, kv.w - h3);
        float4 vv = *(const float4*)(g_v + (gbase + tok) * C + coff + f * 4);
        float4 vt;
        vt.x = __uint_as_float(to_tf32(vv.x));
        vt.y = __uint_as_float(to_tf32(vv.y));
        vt.z = __uint_as_float(to_tf32(vv.z));
        vt.w = __uint_as_float(to_tf32(vv.w));
        *(float4*)(Vs + tok * VP + f * 4) = vt;
    }

    // --- Q (scaled) registers, bf16 hi/lo pairs ---
    int jb = w * 32;
    uint32_t qh[2][2][4], ql[2][2][4];     // [mb][ks][4]
    #pragma unroll
    for (int mb = 0; mb < 2; mb++) {
        int j1 = jb + mb * 16 + g, j2 = j1 + 8;
        #pragma unroll
        for (int ks = 0; ks < 2; ks++) {
            int d0 = 2 * (ks * 8 + t), d1 = 2 * (ks * 8 + t + 4);
            float2 qa = *(const float2*)(g_q + (gbase + j1) * C + coff + d0);
            float2 qb = *(const float2*)(g_q + (gbase + j2) * C + coff + d0);
            float2 qc = *(const float2*)(g_q + (gbase + j1) * C + coff + d1);
            float2 qd = *(const float2*)(g_q + (gbase + j2) * C + coff + d1);
            qa.x *= sc; qa.y *= sc; qb.x *= sc; qb.y *= sc;
            qc.x *= sc; qc.y *= sc; qd.x *= sc; qd.y *= sc;
            float a0 = bf16val(qa.x), a1 = bf16val(qa.y);
            float b0 = bf16val(qb.x), b1 = bf16val(qb.y);
            float c0 = bf16val(qc.x), c1 = bf16val(qc.y);
            float e0 = bf16val(qd.x), e1 = bf16val(qd.y);
            qh[mb][ks][0] = bf16pair(qa.x, qa.y);
            qh[mb][ks][1] = bf16pair(qb.x, qb.y);
            qh[mb][ks][2] = bf16pair(qc.x, qc.y);
            qh[mb][ks][3] = bf16pair(qd.x, qd.y);
            ql[mb][ks][0] = bf16pair(qa.x - a0, qa.y - a1);
            ql[mb][ks][1] = bf16pair(qb.x - b0, qb.y - b1);
            ql[mb][ks][2] = bf16pair(qc.x - c0, qc.y - c1);
            ql[mb][ks][3] = bf16pair(qd.x - e0, qd.y - e1);
        }
    }
    __syncthreads();

    float o[2][4][4];
    #pragma unroll
    for (int mb = 0; mb < 2; mb++)
        #pragma unroll
        for (int nb = 0; nb < 4; nb++)
            #pragma unroll
            for (int r = 0; r < 4; r++) o[mb][nb][r] = 0.0f;
    float lA[2] = {0.f, 0.f}, lB[2] = {0.f, 0.f};

    const float* bth = g_bt + (size_t)h * NT;

    for (int ch = 0; ch < 8; ch++) {
        int tok0 = ch * 32;
        // ---- S = Q K^T (bf16-3x) ----
        float s[2][4][4];
        #pragma unroll
        for (int mb = 0; mb < 2; mb++)
            #pragma unroll
            for (int nt = 0; nt < 4; nt++)
                #pragma unroll
                for (int r = 0; r < 4; r++) s[mb][nt][r] = 0.0f;
        #pragma unroll
        for (int nt = 0; nt < 4; nt++) {
            int tokn = tok0 + nt * 8 + g;
            #pragma unroll
            for (int ks = 0; ks < 2; ks++) {
                uint32_t bh2[2], bl2[2];
                const uint32_t* kh = Kh + tokn * KP + ks * 8;
                const uint32_t* kl = Kl + tokn * KP + ks * 8;
                bh2[0] = kh[t]; bh2[1] = kh[t + 4];
                bl2[0] = kl[t]; bl2[1] = kl[t + 4];
                #pragma unroll
                for (int mb = 0; mb < 2; mb++) {
                    mma_bf16(s[mb][nt], qh[mb][ks], bh2);
                    mma_bf16(s[mb][nt], qh[mb][ks], bl2);
                    mma_bf16(s[mb][nt], ql[mb][ks], bh2);
                }
            }
        }
        // ---- bias + exp + P ----
        #pragma unroll
        for (int mb = 0; mb < 2; mb++) {
            int j1 = jb + mb * 16 + g, j2 = j1 + 8;
            #pragma unroll
            for (int nt = 0; nt < 4; nt++) {
                int k0 = tok0 + nt * 8 + 2 * t;
                float b00 = bth[(size_t)k0 * N + j1];
                float b01 = bth[(size_t)(k0 + 1) * N + j1];
                float b10 = bth[(size_t)k0 * N + j2];
                float b11 = bth[(size_t)(k0 + 1) * N + j2];
                float p0 = __expf(s[mb][nt][0] + b00);
                float p1 = __expf(s[mb][nt][1] + b01);
                float p2 = __expf(s[mb][nt][2] + b10);
                float p3 = __expf(s[mb][nt][3] + b11);
                lA[mb] += p0 + p1;
                lB[mb] += p2 + p3;
                int cc = nt * 8 + 2 * t;
                Pw[(mb*16 + g) * PST + cc]     = __uint_as_float(to_tf32(p0));
                Pw[(mb*16 + g) * PST + cc + 1] = __uint_as_float(to_tf32(p1));
                Pw[(mb*16 + 8 + g) * PST + cc]     = __uint_as_float(to_tf32(p2));
                Pw[(mb*16 + 8 + g) * PST + cc + 1] = __uint_as_float(to_tf32(p3));
            }
        }
        __syncwarp();
        // ---- O += P V (tf32) ----
        #pragma unroll
        for (int ks = 0; ks < 4; ks++) {
            uint32_t pa[2][4];
            #pragma unroll
            for (int mb = 0; mb < 2; mb++) {
                pa[mb][0] = __float_as_uint(Pw[(mb*16 + g) * PST + ks*8 + t]);
                pa[mb][1] = __float_as_uint(Pw[(mb*16 + 8 + g) * PST + ks*8 + t]);
                pa[mb][2] = __float_as_uint(Pw[(mb*16 + g) * PST + ks*8 + t + 4]);
                pa[mb][3] = __float_as_uint(Pw[(mb*16 + 8 + g) * PST + ks*8 + t + 4]);
            }
            #pragma unroll
            for (int nb = 0; nb < 4; nb++) {
                uint32_t vb[2];
                const float* vp = Vs + (tok0 + ks*8) * VP + nb*8 + g;
                vb[0] = __float_as_uint(vp[t * VP]);
                vb[1] = __float_as_uint(vp[(t + 4) * VP]);
                #pragma unroll
                for (int mb = 0; mb < 2; mb++)
                    mma_tf32(o[mb][nb], pa[mb], vb);
            }
        }
        __syncwarp();
    }

    // ---- normalize, gate, store ----
    #pragma unroll
    for (int mb = 0; mb < 2; mb++) {
        lA[mb] += __shfl_xor_sync(0xffffffffu, lA[mb], 1);
        lA[mb] += __shfl_xor_sync(0xffffffffu, lA[mb], 2);
        lB[mb] += __shfl_xor_sync(0xffffffffu, lB[mb], 1);
        lB[mb] += __shfl_xor_sync(0xffffffffu, lB[mb], 2);
        float inv1 = 1.0f / lA[mb], inv2 = 1.0f / lB[mb];
        int j1 = jb + mb * 16 + g, j2 = j1 + 8;
        #pragma unroll
        for (int nb = 0; nb < 4; nb++) {
            int d = nb * 8 + 2 * t;
            float2 g1 = *(const float2*)(g_g + (gbase + j1) * C + coff + d);
            float2 g2 = *(const float2*)(g_g + (gbase + j2) * C + coff + d);
            float2 o1, o2;
            o1.x = g1.x * o[mb][nb][0] * inv1;
            o1.y = g1.y * o[mb][nb][1] * inv1;
            o2.x = g2.x * o[mb][nb][2] * inv2;
            o2.y = g2.y * o[mb][nb][3] * inv2;
            *(float2*)(g_o + (gbase + j1) * C + coff + d) = o1;
            *(float2*)(g_o + (gbase + j2) * C + coff + d) = o2;
        }
    }
}

extern "C" void kernel_launch(void* const* d_in, const int* in_sizes, int n_in,
                              void* d_out, int out_size) {
    const float* z     = (const float*)d_in[0];
    const float* gamma = (const float*)d_in[1];
    const float* beta  = (const float*)d_in[2];
    const float* Wq    = (const float*)d_in[3];
    const float* Wk    = (const float*)d_in[4];
    const float* Wv    = (const float*)d_in[5];
    const float* Wb    = (const float*)d_in[6];
    const float* Wg    = (const float*)d_in[7];
    const float* Wout  = (const float*)d_in[8];
    float* out = (float*)d_out;

    void *p_lnz, *p_q, *p_k, *p_v, *p_g, *p_o;
    cudaGetSymbolAddress(&p_lnz, g_lnz);
    cudaGetSymbolAddress(&p_q, g_q);
    cudaGetSymbolAddress(&p_k, g_k);
    cudaGetSymbolAddress(&p_v, g_v);
    cudaGetSymbolAddress(&p_g, g_g);
    cudaGetSymbolAddress(&p_o, g_o);

    cudaFuncSetAttribute(gemm_fused,
                         cudaFuncAttributeMaxDynamicSharedMemorySize, GEMM_SMEM);
    cudaFuncSetAttribute(attn_mma,
                         cudaFuncAttributeMaxDynamicSharedMemorySize, ATTN_SMEM);

    ln_kernel<<<NT / 8, 256>>>(z, gamma, beta, Wb);
    W5 ws; ws.w[0] = Wq; ws.w[1] = Wk; ws.w[2] = Wv; ws.w[3] = Wg; ws.w[4] = Wout;
    wprep_kernel<<<dim3(32, 5), 256>>>(ws);

    Y4 yq; yq.p[0] = (float*)p_q; yq.p[1] = (float*)p_k;
    yq.p[2] = (float*)p_v; yq.p[3] = (float*)p_g;
    gemm_fused<<<NT / 128, 256, GEMM_SMEM>>>((const float*)p_lnz, 0, 4, yq, 0x8);

    attn_mma<<<dim3(N, H), 256, ATTN_SMEM>>>();

    Y4 yo; yo.p[0] = out; yo.p[1] = yo.p[2] = yo.p[3] = nullptr;
    gemm_fused<<<NT / 128, 256, GEMM_SMEM>>>((const float*)p_o, 4, 1, yo, 0);
}

// round 9
// speedup vs baseline: 1.2832x; 1.0380x over previous
#include <cuda_runtime.h>
#include <cuda_bf16.h>
#include <math.h>
#include <stdint.h>

#define N 256
#define NT (N*N)
#define C 128
#define H 4
#define D 32

// -------- scratch (device globals; no allocation allowed) --------
__device__ float    g_lnz[NT*C];
__device__ float    g_q[NT*C];
__device__ float    g_k[NT*C];
__device__ float    g_v[NT*C];
__device__ float    g_g[NT*C];     // sigmoid(z@Wg)
__device__ float    g_bt[H*NT];    // bias transposed: [h][k][j]
__device__ float    g_o[NT*C];     // gated attention output
__device__ uint32_t g_wph[5*C*(C/2)];
__device__ uint32_t g_wpl[5*C*(C/2)];

struct Y4 { float* p[4]; };
struct W5 { const float* w[5]; };

// ---------- helpers ----------
__device__ __forceinline__ float bf16val(float x) {
    return __bfloat162float(__float2bfloat16(x));
}
__device__ __forceinline__ uint32_t bf16pair(float even, float odd) {
    uint32_t r;
    asm("cvt.rn.satfinite.bf16x2.f32 %0, %1, %2;" : "=r"(r) : "f"(odd), "f"(even));
    return r;
}
__device__ __forceinline__ void mma_bf16(float* c, const uint32_t* a,
                                         const uint32_t* b) {
    asm volatile(
        "mma.sync.aligned.m16n8k16.row.col.f32.bf16.bf16.f32 "
        "{%0,%1,%2,%3},{%4,%5,%6,%7},{%8,%9},{%0,%1,%2,%3};"
        : "+f"(c[0]), "+f"(c[1]), "+f"(c[2]), "+f"(c[3])
        : "r"(a[0]), "r"(a[1]), "r"(a[2]), "r"(a[3]), "r"(b[0]), "r"(b[1]));
}
__device__ __forceinline__ uint32_t to_tf32(float x) {
    uint32_t u;
    asm("cvt.rna.tf32.f32 %0, %1;" : "=r"(u) : "f"(x));
    return u;
}
__device__ __forceinline__ void mma_tf32(float* c, const uint32_t* a,
                                         const uint32_t* b) {
    asm volatile(
        "mma.sync.aligned.m16n8k8.row.col.f32.tf32.tf32.f32 "
        "{%0,%1,%2,%3},{%4,%5,%6,%7},{%8,%9},{%0,%1,%2,%3};"
        : "+f"(c[0]), "+f"(c[1]), "+f"(c[2]), "+f"(c[3])
        : "r"(a[0]), "r"(a[1]), "r"(a[2]), "r"(a[3]), "r"(b[0]), "r"(b[1]));
}
__device__ __forceinline__ void cp16(uint32_t* smem_dst, const void* gsrc) {
    uint32_t s = (uint32_t)__cvta_generic_to_shared(smem_dst);
    asm volatile("cp.async.cg.shared.global [%0], [%1], 16;\n"
                 :: "r"(s), "l"(gsrc));
}

// ---------------- LayerNorm + fused bias projection ----------------
__global__ void ln_kernel(const float* __restrict__ z,
                          const float* __restrict__ gamma,
                          const float* __restrict__ beta,
                          const float* __restrict__ Wb) {
    int warp = threadIdx.x >> 5, lane = threadIdx.x & 31;
    int t = blockIdx.x * 8 + warp;
    const float4 v = *(const float4*)(z + (size_t)t * C + lane * 4);
    float s = v.x + v.y + v.z + v.w;
    #pragma unroll
    for (int o = 16; o; o >>= 1) s += __shfl_xor_sync(0xffffffffu, s, o);
    float mu = s * (1.0f / C);
    float d0 = v.x - mu, d1 = v.y - mu, d2 = v.z - mu, d3 = v.w - mu;
    float vs = d0*d0 + d1*d1 + d2*d2 + d3*d3;
    #pragma unroll
    for (int o = 16; o; o >>= 1) vs += __shfl_xor_sync(0xffffffffu, vs, o);
    float r = rsqrtf(vs * (1.0f / C) + 1e-5f);
    float4 gm = *(const float4*)(gamma + lane * 4);
    float4 bt = *(const float4*)(beta + lane * 4);
    float4 out;
    out.x = d0 * r * gm.x + bt.x;
    out.y = d1 * r * gm.y + bt.y;
    out.z = d2 * r * gm.z + bt.z;
    out.w = d3 * r * gm.w + bt.w;
    *(float4*)(g_lnz + (size_t)t * C + lane * 4) = out;

    float4 w0 = *(const float4*)(Wb + lane * 16);
    float4 w1 = *(const float4*)(Wb + lane * 16 + 4);
    float4 w2 = *(const float4*)(Wb + lane * 16 + 8);
    float4 w3 = *(const float4*)(Wb + lane * 16 + 12);
    float4 p;
    p.x = out.x * w0.x + out.y * w1.x + out.z * w2.x + out.w * w3.x;
    p.y = out.x * w0.y + out.y * w1.y + out.z * w2.y + out.w * w3.y;
    p.z = out.x * w0.z + out.y * w1.z + out.z * w2.z + out.w * w3.z;
    p.w = out.x * w0.w + out.y * w1.w + out.z * w2.w + out.w * w3.w;
    #pragma unroll
    for (int o = 16; o; o >>= 1) {
        p.x += __shfl_xor_sync(0xffffffffu, p.x, o);
        p.y += __shfl_xor_sync(0xffffffffu, p.y, o);
        p.z += __shfl_xor_sync(0xffffffffu, p.z, o);
        p.w += __shfl_xor_sync(0xffffffffu, p.w, o);
    }
    if (lane == 0) {
        int j = t >> 8, k = t & 255;
        g_bt[((size_t)0 * N + k) * N + j] = p.x;
        g_bt[((size_t)1 * N + k) * N + j] = p.y;
        g_bt[((size_t)2 * N + k) * N + j] = p.z;
        g_bt[((size_t)3 * N + k) * N + j] = p.w;
    }
}

// ------- weight prep: split + pack + transpose -------
__global__ void wprep_kernel(W5 ws) {
    int mat = blockIdx.y;
    int idx = blockIdx.x * 256 + threadIdx.x;
    int n = idx >> 6, k2 = idx & 63;
    const float* W = ws.w[mat];
    float w0 = W[(2 * k2) * C + n];
    float w1 = W[(2 * k2 + 1) * C + n];
    float h0 = bf16val(w0), h1 = bf16val(w1);
    g_wph[mat * 8192 + n * 64 + k2] = bf16pair(w0, w1);
    g_wpl[mat * 8192 + n * 64 + k2] = bf16pair(w0 - h0, w1 - h1);
}

// ---------------- fused bf16-3x GEMM: 512 threads, 16 warps ----------------
#define XW 68
#define XPLANE (128 * XW)
#define WBUF (2 * XPLANE)
#define GEMM_SMEM ((2 * XPLANE + 2 * WBUF) * 4)
#define GT 512

__global__ void __launch_bounds__(GT, 1)
gemm_fused(const float* __restrict__ X, int slot0, int nmat, Y4 ys, int sigmask) {
    extern __shared__ uint32_t sm4[];
    uint32_t* Xh2 = sm4;
    uint32_t* Xl2 = sm4 + XPLANE;
    uint32_t* Wb  = sm4 + 2 * XPLANE;

    int tid = threadIdx.x;
    int warp = tid >> 5, lane = tid & 31;
    int g = lane >> 2, t = lane & 3;
    int wm = warp >> 2, wn = warp & 3;   // 4x4 warp grid, warp tile 32x32
    int row0 = blockIdx.x * 128;

    auto issueW = [&](int s, int buf) {
        uint32_t* wb = Wb + buf * WBUF;
        #pragma unroll
        for (int i = 0; i < 8; i++) {
            int id = tid + i * GT;
            int plane = id >> 11, r = id & 2047;
            int n = r >> 4, q = r & 15;
            const uint32_t* src =
                (plane ? g_wpl : g_wph) + (slot0 + s) * 8192 + n * 64 + q * 4;
            cp16(wb + plane * XPLANE + n * XW + q * 4, src);
        }
    };

    issueW(0, 0);
    asm volatile("cp.async.commit_group;\n");
    #pragma unroll
    for (int i = 0; i < 8; i++) {
        int id = tid + i * GT;
        int row = id >> 5, c4 = id & 31;
        float4 v = *(const float4*)(X + (size_t)(row0 + row) * C + c4 * 4);
        float h0 = bf16val(v.x), h1 = bf16val(v.y);
        float h2 = bf16val(v.z), h3 = bf16val(v.w);
        uint32_t* xh = Xh2 + row * XW + c4 * 2;
        uint32_t* xl = Xl2 + row * XW + c4 * 2;
        xh[0] = bf16pair(v.x, v.y);
        xh[1] = bf16pair(v.z, v.w);
        xl[0] = bf16pair(v.x - h0, v.y - h1);
        xl[1] = bf16pair(v.z - h2, v.w - h3);
    }

    #pragma unroll 1
    for (int s = 0; s < nmat; s++) {
        if (s + 1 < nmat) {
            issueW(s + 1, (s + 1) & 1);
            asm volatile("cp.async.commit_group;\n");
            asm volatile("cp.async.wait_group 1;\n");
        } else {
            asm volatile("cp.async.wait_group 0;\n");
        }
        __syncthreads();

        uint32_t* Wh2 = Wb + (s & 1) * WBUF;
        uint32_t* Wl2 = Wh2 + XPLANE;

        float c[2][4][4];
        #pragma unroll
        for (int mb = 0; mb < 2; mb++)
            #pragma unroll
            for (int nb = 0; nb < 4; nb++)
                #pragma unroll
                for (int r = 0; r < 4; r++) c[mb][nb][r] = 0.0f;

        #pragma unroll
        for (int ks = 0; ks < 8; ks++) {
            int kb = ks * 8;
            uint32_t bh[4][2], bl[4][2];
            #pragma unroll
            for (int nb = 0; nb < 4; nb++) {
                int n = wn * 32 + nb * 8 + g;
                bh[nb][0] = Wh2[n * XW + kb + t];
                bh[nb][1] = Wh2[n * XW + kb + t + 4];
                bl[nb][0] = Wl2[n * XW + kb + t];
                bl[nb][1] = Wl2[n * XW + kb + t + 4];
            }
            #pragma unroll
            for (int mb = 0; mb < 2; mb++) {
                int r = wm * 32 + mb * 16 + g;
                uint32_t ah[4], al[4];
                ah[0] = Xh2[r * XW + kb + t];
                ah[1] = Xh2[(r + 8) * XW + kb + t];
                ah[2] = Xh2[r * XW + kb + t + 4];
                ah[3] = Xh2[(r + 8) * XW + kb + t + 4];
                al[0] = Xl2[r * XW + kb + t];
                al[1] = Xl2[(r + 8) * XW + kb + t];
                al[2] = Xl2[r * XW + kb + t + 4];
                al[3] = Xl2[(r + 8) * XW + kb + t + 4];
                #pragma unroll
                for (int nb = 0; nb < 4; nb++) {
                    mma_bf16(c[mb][nb], ah, bh[nb]);
                    mma_bf16(c[mb][nb], ah, bl[nb]);
                    mma_bf16(c[mb][nb], al, bh[nb]);
                }
            }
        }

        float* Y = ys.p[s];
        int sg = (sigmask >> s) & 1;
        #pragma unroll
        for (int mb = 0; mb < 2; mb++) {
            int r0 = row0 + wm * 32 + mb * 16 + g;
            #pragma unroll
            for (int nb = 0; nb < 4; nb++) {
                int col = wn * 32 + nb * 8 + 2 * t;
                float v0 = c[mb][nb][0], v1 = c[mb][nb][1];
                float v2 = c[mb][nb][2], v3 = c[mb][nb][3];
                if (sg) {
                    v0 = 1.0f / (1.0f + __expf(-v0));
                    v1 = 1.0f / (1.0f + __expf(-v1));
                    v2 = 1.0f / (1.0f + __expf(-v2));
                    v3 = 1.0f / (1.0f + __expf(-v3));
                }
                *(float2*)(Y + (size_t)r0 * C + col) = make_float2(v0, v1);
                *(float2*)(Y + (size_t)(r0 + 8) * C + col) = make_float2(v2, v3);
            }
        }
        __syncthreads();
    }
}

// ---------------- attention: 512 threads, 16 warps x m16 ----------------
#define KP 20
#define VP 40
#define PST 36
#define KPL (256 * KP)
#define VPL (256 * VP)
#define AT 512
#define ATTN_SMEM ((2 * KPL + VPL + 16 * 16 * PST) * 4)   // 118784 B

__global__ void __launch_bounds__(AT, 1)
attn_mma() {
    extern __shared__ uint32_t smu[];
    uint32_t* Kh = smu;                    // [256][KP] bf16 pairs
    uint32_t* Kl = smu + KPL;
    float* Vs = (float*)(smu + 2 * KPL);   // [256][VP] tf32
    float* Ps = (float*)(smu + 2 * KPL + VPL);  // 16 warps x [16][PST]

    int i = blockIdx.x, h = blockIdx.y;
    int tid = threadIdx.x;
    int w = tid >> 5, lane = tid & 31;
    int g = lane >> 2, t = lane & 3;
    int coff = h * D;
    size_t gbase = (size_t)i * N;
    float* Pw = Ps + w * 16 * PST;
    const float sc = 0.17677669529663687f;

    // --- stage K (bf16 hi/lo pairs) and V (tf32) ---
    #pragma unroll
    for (int it = 0; it < 4; it++) {
        int idx = tid + it * AT;
        int tok = idx >> 3, f = idx & 7;
        float4 kv = *(const float4*)(g_k + (gbase + tok) * C + coff + f * 4);
        float h0 = bf16val(kv.x), h1 = bf16val(kv.y);
        float h2 = bf16val(kv.z), h3 = bf16val(kv.w);
        uint32_t* kh = Kh + tok * KP + f * 2;
        uint32_t* kl = Kl + tok * KP + f * 2;
        kh[0] = bf16pair(kv.x, kv.y);
        kh[1] = bf16pair(kv.z, kv.w);
        kl[0] = bf16pair(kv.x - h0, kv.y - h1);
        kl[1] = bf16pair(kv.z - h2, kv.w - h3);
        float4 vv = *(const float4*)(g_v + (gbase + tok) * C + coff + f * 4);
        float4 vt;
        vt.x = __uint_as_float(to_tf32(vv.x));
        vt.y = __uint_as_float(to_tf32(vv.y));
        vt.z = __uint_as_float(to_tf32(vv.z));
        vt.w = __uint_as_float(to_tf32(vv.w));
        *(float4*)(Vs + tok * VP + f * 4) = vt;
    }

    // --- Q (scaled) registers, bf16 hi/lo pairs (warp owns 16 rows) ---
    int jb = w * 16;
    int j1 = jb + g, j2 = jb + 8 + g;
    uint32_t qh[2][4], ql[2][4];
    #pragma unroll
    for (int ks = 0; ks < 2; ks++) {
        int d0 = 2 * (ks * 8 + t), d1 = 2 * (ks * 8 + t + 4);
        float2 qa = *(const float2*)(g_q + (gbase + j1) * C + coff + d0);
        float2 qb = *(const float2*)(g_q + (gbase + j2) * C + coff + d0);
        float2 qc = *(const float2*)(g_q + (gbase + j1) * C + coff + d1);
        float2 qd = *(const float2*)(g_q + (gbase + j2) * C + coff + d1);
        qa.x *= sc; qa.y *= sc; qb.x *= sc; qb.y *= sc;
        qc.x *= sc; qc.y *= sc; qd.x *= sc; qd.y *= sc;
        float a0 = bf16val(qa.x), a1 = bf16val(qa.y);
        float b0 = bf16val(qb.x), b1 = bf16val(qb.y);
        float c0 = bf16val(qc.x), c1 = bf16val(qc.y);
        float e0 = bf16val(qd.x), e1 = bf16val(qd.y);
        qh[ks][0] = bf16pair(qa.x, qa.y);
        qh[ks][1] = bf16pair(qb.x, qb.y);
        qh[ks][2] = bf16pair(qc.x, qc.y);
        qh[ks][3] = bf16pair(qd.x, qd.y);
        ql[ks][0] = bf16pair(qa.x - a0, qa.y - a1);
        ql[ks][1] = bf16pair(qb.x - b0, qb.y - b1);
        ql[ks][2] = bf16pair(qc.x - c0, qc.y - c1);
        ql[ks][3] = bf16pair(qd.x - e0, qd.y - e1);
    }
    __syncthreads();

    float o[4][4];
    #pragma unroll
    for (int nb = 0; nb < 4; nb++)
        #pragma unroll
        for (int r = 0; r < 4; r++) o[nb][r] = 0.0f;
    float lA = 0.f, lB = 0.f;

    const float* bth = g_bt + (size_t)h * NT;

    for (int ch = 0; ch < 8; ch++) {
        int tok0 = ch * 32;
        // ---- S = Q K^T (bf16-3x) ----
        float s[4][4];
        #pragma unroll
        for (int nt = 0; nt < 4; nt++)
            #pragma unroll
            for (int r = 0; r < 4; r++) s[nt][r] = 0.0f;
        #pragma unroll
        for (int nt = 0; nt < 4; nt++) {
            int tokn = tok0 + nt * 8 + g;
            #pragma unroll
            for (int ks = 0; ks < 2; ks++) {
                uint32_t bh2[2], bl2[2];
                const uint32_t* kh = Kh + tokn * KP + ks * 8;
                const uint32_t* kl = Kl + tokn * KP + ks * 8;
                bh2[0] = kh[t]; bh2[1] = kh[t + 4];
                bl2[0] = kl[t]; bl2[1] = kl[t + 4];
                mma_bf16(s[nt], qh[ks], bh2);
                mma_bf16(s[nt], qh[ks], bl2);
                mma_bf16(s[nt], ql[ks], bh2);
            }
        }
        // ---- bias + exp + P ----
        #pragma unroll
        for (int nt = 0; nt < 4; nt++) {
            int k0 = tok0 + nt * 8 + 2 * t;
            float b00 = bth[(size_t)k0 * N + j1];
            float b01 = bth[(size_t)(k0 + 1) * N + j1];
            float b10 = bth[(size_t)k0 * N + j2];
            float b11 = bth[(size_t)(k0 + 1) * N + j2];
            float p0 = __expf(s[nt][0] + b00);
            float p1 = __expf(s[nt][1] + b01);
            float p2 = __expf(s[nt][2] + b10);
            float p3 = __expf(s[nt][3] + b11);
            lA += p0 + p1;
            lB += p2 + p3;
            int cc = nt * 8 + 2 * t;
            Pw[g * PST + cc]     = __uint_as_float(to_tf32(p0));
            Pw[g * PST + cc + 1] = __uint_as_float(to_tf32(p1));
            Pw[(8 + g) * PST + cc]     = __uint_as_float(to_tf32(p2));
            Pw[(8 + g) * PST + cc + 1] = __uint_as_float(to_tf32(p3));
        }
        __syncwarp();
        // ---- O += P V (tf32) ----
        #pragma unroll
        for (int ks = 0; ks < 4; ks++) {
            uint32_t pa[4];
            pa[0] = __float_as_uint(Pw[g * PST + ks*8 + t]);
            pa[1] = __float_as_uint(Pw[(8 + g) * PST + ks*8 + t]);
            pa[2] = __float_as_uint(Pw[g * PST + ks*8 + t + 4]);
            pa[3] = __float_as_uint(Pw[(8 + g) * PST + ks*8 + t + 4]);
            #pragma unroll
            for (int nb = 0; nb < 4; nb++) {
                uint32_t vb[2];
                const float* vp = Vs + (tok0 + ks*8) * VP + nb*8 + g;
                vb[0] = __float_as_uint(vp[t * VP]);
                vb[1] = __float_as_uint(vp[(t + 4) * VP]);
                mma_tf32(o[nb], pa, vb);
            }
        }
        __syncwarp();
    }

    // ---- normalize, gate, store ----
    lA += __shfl_xor_sync(0xffffffffu, lA, 1);
    lA += __shfl_xor_sync(0xffffffffu, lA, 2);
    lB += __shfl_xor_sync(0xffffffffu, lB, 1);
    lB += __shfl_xor_sync(0xffffffffu, lB, 2);
    float inv1 = 1.0f / lA, inv2 = 1.0f / lB;
    #pragma unroll
    for (int nb = 0; nb < 4; nb++) {
        int d = nb * 8 + 2 * t;
        float2 g1 = *(const float2*)(g_g + (gbase + j1) * C + coff + d);
        float2 g2 = *(const float2*)(g_g + (gbase + j2) * C + coff + d);
        float2 o1, o2;
        o1.x = g1.x * o[nb][0] * inv1;
        o1.y = g1.y * o[nb][1] * inv1;
        o2.x = g2.x * o[nb][2] * inv2;
        o2.y = g2.y * o[nb][3] * inv2;
        *(float2*)(g_o + (gbase + j1) * C + coff + d) = o1;
        *(float2*)(g_o + (gbase + j2) * C + coff + d) = o2;
    }
}

extern "C" void kernel_launch(void* const* d_in, const int* in_sizes, int n_in,
                              void* d_out, int out_size) {
    const float* z     = (const float*)d_in[0];
    const float* gamma = (const float*)d_in[1];
    const float* beta  = (const float*)d_in[2];
    const float* Wq    = (const float*)d_in[3];
    const float* Wk    = (const float*)d_in[4];
    const float* Wv    = (const float*)d_in[5];
    const float* Wb    = (const float*)d_in[6];
    const float* Wg    = (const float*)d_in[7];
    const float* Wout  = (const float*)d_in[8];
    float* out = (float*)d_out;

    void *p_lnz, *p_q, *p_k, *p_v, *p_g, *p_o;
    cudaGetSymbolAddress(&p_lnz, g_lnz);
    cudaGetSymbolAddress(&p_q, g_q);
    cudaGetSymbolAddress(&p_k, g_k);
    cudaGetSymbolAddress(&p_v, g_v);
    cudaGetSymbolAddress(&p_g, g_g);
    cudaGetSymbolAddress(&p_o, g_o);

    cudaFuncSetAttribute(gemm_fused,
                         cudaFuncAttributeMaxDynamicSharedMemorySize, GEMM_SMEM);
    cudaFuncSetAttribute(attn_mma,
                         cudaFuncAttributeMaxDynamicSharedMemorySize, ATTN_SMEM);

    ln_kernel<<<NT / 8, 256>>>(z, gamma, beta, Wb);
    W5 ws; ws.w[0] = Wq; ws.w[1] = Wk; ws.w[2] = Wv; ws.w[3] = Wg; ws.w[4] = Wout;
    wprep_kernel<<<dim3(32, 5), 256>>>(ws);

    Y4 yq; yq.p[0] = (float*)p_q; yq.p[1] = (float*)p_k;
    yq.p[2] = (float*)p_v; yq.p[3] = (float*)p_g;
    gemm_fused<<<NT / 128, GT, GEMM_SMEM>>>((const float*)p_lnz, 0, 4, yq, 0x8);

    attn_mma<<<dim3(N, H), AT, ATTN_SMEM>>>();

    Y4 yo; yo.p[0] = out; yo.p[1] = yo.p[2] = yo.p[3] = nullptr;
    gemm_fused<<<NT / 128, GT, GEMM_SMEM>>>((const float*)p_o, 4, 1, yo, 0);
}

// round 10
// speedup vs baseline: 1.3093x; 1.0203x over previous
#include <cuda_runtime.h>
#include <cuda_bf16.h>
#include <math.h>
#include <stdint.h>

#define N 256
#define NT (N*N)
#define C 128
#define H 4
#define D 32

// -------- scratch (device globals; no allocation allowed) --------
__device__ float    g_lnz[NT*C];
__device__ float    g_q[NT*C];
__device__ float    g_k[NT*C];
__device__ float    g_v[NT*C];
__device__ float    g_g[NT*C];     // sigmoid(z@Wg)
__device__ float    g_bt[H*NT];    // bias transposed: [h][k][j]
__device__ float    g_o[NT*C];     // gated attention output
__device__ uint32_t g_wph[5*C*(C/2)];
__device__ uint32_t g_wpl[5*C*(C/2)];

struct Y4 { float* p[4]; };
struct W5 { const float* w[5]; };

// ---------- helpers ----------
__device__ __forceinline__ float bf16val(float x) {
    return __bfloat162float(__float2bfloat16(x));
}
__device__ __forceinline__ uint32_t bf16pair(float even, float odd) {
    uint32_t r;
    asm("cvt.rn.satfinite.bf16x2.f32 %0, %1, %2;" : "=r"(r) : "f"(odd), "f"(even));
    return r;
}
__device__ __forceinline__ void mma_bf16(float* c, const uint32_t* a,
                                         const uint32_t* b) {
    asm volatile(
        "mma.sync.aligned.m16n8k16.row.col.f32.bf16.bf16.f32 "
        "{%0,%1,%2,%3},{%4,%5,%6,%7},{%8,%9},{%0,%1,%2,%3};"
        : "+f"(c[0]), "+f"(c[1]), "+f"(c[2]), "+f"(c[3])
        : "r"(a[0]), "r"(a[1]), "r"(a[2]), "r"(a[3]), "r"(b[0]), "r"(b[1]));
}
__device__ __forceinline__ void cp16(uint32_t* smem_dst, const void* gsrc) {
    uint32_t s = (uint32_t)__cvta_generic_to_shared(smem_dst);
    asm volatile("cp.async.cg.shared.global [%0], [%1], 16;\n"
                 :: "r"(s), "l"(gsrc));
}

// ---------------- LayerNorm + fused bias projection ----------------
__global__ void ln_kernel(const float* __restrict__ z,
                          const float* __restrict__ gamma,
                          const float* __restrict__ beta,
                          const float* __restrict__ Wb) {
    int warp = threadIdx.x >> 5, lane = threadIdx.x & 31;
    int t = blockIdx.x * 8 + warp;
    const float4 v = *(const float4*)(z + (size_t)t * C + lane * 4);
    float s = v.x + v.y + v.z + v.w;
    #pragma unroll
    for (int o = 16; o; o >>= 1) s += __shfl_xor_sync(0xffffffffu, s, o);
    float mu = s * (1.0f / C);
    float d0 = v.x - mu, d1 = v.y - mu, d2 = v.z - mu, d3 = v.w - mu;
    float vs = d0*d0 + d1*d1 + d2*d2 + d3*d3;
    #pragma unroll
    for (int o = 16; o; o >>= 1) vs += __shfl_xor_sync(0xffffffffu, vs, o);
    float r = rsqrtf(vs * (1.0f / C) + 1e-5f);
    float4 gm = *(const float4*)(gamma + lane * 4);
    float4 bt = *(const float4*)(beta + lane * 4);
    float4 out;
    out.x = d0 * r * gm.x + bt.x;
    out.y = d1 * r * gm.y + bt.y;
    out.z = d2 * r * gm.z + bt.z;
    out.w = d3 * r * gm.w + bt.w;
    *(float4*)(g_lnz + (size_t)t * C + lane * 4) = out;

    float4 w0 = *(const float4*)(Wb + lane * 16);
    float4 w1 = *(const float4*)(Wb + lane * 16 + 4);
    float4 w2 = *(const float4*)(Wb + lane * 16 + 8);
    float4 w3 = *(const float4*)(Wb + lane * 16 + 12);
    float4 p;
    p.x = out.x * w0.x + out.y * w1.x + out.z * w2.x + out.w * w3.x;
    p.y = out.x * w0.y + out.y * w1.y + out.z * w2.y + out.w * w3.y;
    p.z = out.x * w0.z + out.y * w1.z + out.z * w2.z + out.w * w3.z;
    p.w = out.x * w0.w + out.y * w1.w + out.z * w2.w + out.w * w3.w;
    #pragma unroll
    for (int o = 16; o; o >>= 1) {
        p.x += __shfl_xor_sync(0xffffffffu, p.x, o);
        p.y += __shfl_xor_sync(0xffffffffu, p.y, o);
        p.z += __shfl_xor_sync(0xffffffffu, p.z, o);
        p.w += __shfl_xor_sync(0xffffffffu, p.w, o);
    }
    if (lane == 0) {
        int j = t >> 8, k = t & 255;
        g_bt[((size_t)0 * N + k) * N + j] = p.x;
        g_bt[((size_t)1 * N + k) * N + j] = p.y;
        g_bt[((size_t)2 * N + k) * N + j] = p.z;
        g_bt[((size_t)3 * N + k) * N + j] = p.w;
    }
}

// ------- weight prep: split + pack + transpose -------
__global__ void wprep_kernel(W5 ws) {
    int mat = blockIdx.y;
    int idx = blockIdx.x * 256 + threadIdx.x;
    int n = idx >> 6, k2 = idx & 63;
    const float* W = ws.w[mat];
    float w0 = W[(2 * k2) * C + n];
    float w1 = W[(2 * k2 + 1) * C + n];
    float h0 = bf16val(w0), h1 = bf16val(w1);
    g_wph[mat * 8192 + n * 64 + k2] = bf16pair(w0, w1);
    g_wpl[mat * 8192 + n * 64 + k2] = bf16pair(w0 - h0, w1 - h1);
}

// ---------------- fused bf16-3x GEMM: 512 threads, 16 warps ----------------
#define XW 68
#define XPLANE (128 * XW)
#define WBUF (2 * XPLANE)
#define GEMM_SMEM ((2 * XPLANE + 2 * WBUF) * 4)
#define GT 512

__global__ void __launch_bounds__(GT, 1)
gemm_fused(const float* __restrict__ X, int slot0, int nmat, Y4 ys, int sigmask) {
    extern __shared__ uint32_t sm4[];
    uint32_t* Xh2 = sm4;
    uint32_t* Xl2 = sm4 + XPLANE;
    uint32_t* Wb  = sm4 + 2 * XPLANE;

    int tid = threadIdx.x;
    int warp = tid >> 5, lane = tid & 31;
    int g = lane >> 2, t = lane & 3;
    int wm = warp >> 2, wn = warp & 3;
    int row0 = blockIdx.x * 128;

    auto issueW = [&](int s, int buf) {
        uint32_t* wb = Wb + buf * WBUF;
        #pragma unroll
        for (int i = 0; i < 8; i++) {
            int id = tid + i * GT;
            int plane = id >> 11, r = id & 2047;
            int n = r >> 4, q = r & 15;
            const uint32_t* src =
                (plane ? g_wpl : g_wph) + (slot0 + s) * 8192 + n * 64 + q * 4;
            cp16(wb + plane * XPLANE + n * XW + q * 4, src);
        }
    };

    issueW(0, 0);
    asm volatile("cp.async.commit_group;\n");
    #pragma unroll
    for (int i = 0; i < 8; i++) {
        int id = tid + i * GT;
        int row = id >> 5, c4 = id & 31;
        float4 v = *(const float4*)(X + (size_t)(row0 + row) * C + c4 * 4);
        float h0 = bf16val(v.x), h1 = bf16val(v.y);
        float h2 = bf16val(v.z), h3 = bf16val(v.w);
        uint32_t* xh = Xh2 + row * XW + c4 * 2;
        uint32_t* xl = Xl2 + row * XW + c4 * 2;
        xh[0] = bf16pair(v.x, v.y);
        xh[1] = bf16pair(v.z, v.w);
        xl[0] = bf16pair(v.x - h0, v.y - h1);
        xl[1] = bf16pair(v.z - h2, v.w - h3);
    }

    #pragma unroll 1
    for (int s = 0; s < nmat; s++) {
        if (s + 1 < nmat) {
            issueW(s + 1, (s + 1) & 1);
            asm volatile("cp.async.commit_group;\n");
            asm volatile("cp.async.wait_group 1;\n");
        } else {
            asm volatile("cp.async.wait_group 0;\n");
        }
        __syncthreads();

        uint32_t* Wh2 = Wb + (s & 1) * WBUF;
        uint32_t* Wl2 = Wh2 + XPLANE;

        float c[2][4][4];
        #pragma unroll
        for (int mb = 0; mb < 2; mb++)
            #pragma unroll
            for (int nb = 0; nb < 4; nb++)
                #pragma unroll
                for (int r = 0; r < 4; r++) c[mb][nb][r] = 0.0f;

        #pragma unroll
        for (int ks = 0; ks < 8; ks++) {
            int kb = ks * 8;
            uint32_t bh[4][2], bl[4][2];
            #pragma unroll
            for (int nb = 0; nb < 4; nb++) {
                int n = wn * 32 + nb * 8 + g;
                bh[nb][0] = Wh2[n * XW + kb + t];
                bh[nb][1] = Wh2[n * XW + kb + t + 4];
                bl[nb][0] = Wl2[n * XW + kb + t];
                bl[nb][1] = Wl2[n * XW + kb + t + 4];
            }
            #pragma unroll
            for (int mb = 0; mb < 2; mb++) {
                int r = wm * 32 + mb * 16 + g;
                uint32_t ah[4], al[4];
                ah[0] = Xh2[r * XW + kb + t];
                ah[1] = Xh2[(r + 8) * XW + kb + t];
                ah[2] = Xh2[r * XW + kb + t + 4];
                ah[3] = Xh2[(r + 8) * XW + kb + t + 4];
                al[0] = Xl2[r * XW + kb + t];
                al[1] = Xl2[(r + 8) * XW + kb + t];
                al[2] = Xl2[r * XW + kb + t + 4];
                al[3] = Xl2[(r + 8) * XW + kb + t + 4];
                #pragma unroll
                for (int nb = 0; nb < 4; nb++) {
                    mma_bf16(c[mb][nb], ah, bh[nb]);
                    mma_bf16(c[mb][nb], ah, bl[nb]);
                    mma_bf16(c[mb][nb], al, bh[nb]);
                }
            }
        }

        float* Y = ys.p[s];
        int sg = (sigmask >> s) & 1;
        #pragma unroll
        for (int mb = 0; mb < 2; mb++) {
            int r0 = row0 + wm * 32 + mb * 16 + g;
            #pragma unroll
            for (int nb = 0; nb < 4; nb++) {
                int col = wn * 32 + nb * 8 + 2 * t;
                float v0 = c[mb][nb][0], v1 = c[mb][nb][1];
                float v2 = c[mb][nb][2], v3 = c[mb][nb][3];
                if (sg) {
                    v0 = 1.0f / (1.0f + __expf(-v0));
                    v1 = 1.0f / (1.0f + __expf(-v1));
                    v2 = 1.0f / (1.0f + __expf(-v2));
                    v3 = 1.0f / (1.0f + __expf(-v3));
                }
                *(float2*)(Y + (size_t)r0 * C + col) = make_float2(v0, v1);
                *(float2*)(Y + (size_t)(r0 + 8) * C + col) = make_float2(v2, v3);
            }
        }
        __syncthreads();
    }
}

// ---------------- attention: all-bf16-compensated, P in registers ----------------
// QK^T: bf16-3x (K pairs along d). PV: bf16-3x (P hi/lo in registers from the
// S fragment; V hi/lo token-paired in smem). No P smem round-trip, no syncwarp.
#define KP 20     // K pair-row stride (words): banks (20g+t)%32 distinct
#define VS 40     // V pair-row stride: banks (8t+g) distinct
#define KPL (256 * KP)
#define VPL (128 * VS)
#define AT 512
#define ATTN_SMEM ((2 * KPL + 2 * VPL) * 4)   // 81920 B

__global__ void __launch_bounds__(AT, 1)
attn_mma() {
    extern __shared__ uint32_t smu[];
    uint32_t* Kh  = smu;                 // [256 tok][KP] bf16 pairs along d
    uint32_t* Kl  = smu + KPL;
    uint32_t* Vph = smu + 2 * KPL;       // [128 tokpair][VS] bf16 pairs along tok
    uint32_t* Vpl = Vph + VPL;

    int i = blockIdx.x, h = blockIdx.y;
    int tid = threadIdx.x;
    int w = tid >> 5, lane = tid & 31;
    int g = lane >> 2, t = lane & 3;
    int coff = h * D;
    size_t gbase = (size_t)i * N;
    const float sc = 0.17677669529663687f;

    // --- stage K: pairs along d (hi/lo) ---
    #pragma unroll
    for (int it = 0; it < 4; it++) {
        int idx = tid + it * AT;
        int tok = idx >> 3, f = idx & 7;
        float4 kv = *(const float4*)(g_k + (gbase + tok) * C + coff + f * 4);
        float h0 = bf16val(kv.x), h1 = bf16val(kv.y);
        float h2 = bf16val(kv.z), h3 = bf16val(kv.w);
        uint32_t* kh = Kh + tok * KP + f * 2;
        uint32_t* kl = Kl + tok * KP + f * 2;
        kh[0] = bf16pair(kv.x, kv.y);
        kh[1] = bf16pair(kv.z, kv.w);
        kl[0] = bf16pair(kv.x - h0, kv.y - h1);
        kl[1] = bf16pair(kv.z - h2, kv.w - h3);
    }
    // --- stage V: pairs along tokens (hi/lo) ---
    #pragma unroll
    for (int it = 0; it < 2; it++) {
        int idx = tid + it * AT;           // 0..1023
        int m = idx >> 3, q = idx & 7;     // tokpair, col quad (4 cols)
        size_t b0 = (gbase + 2 * m) * C + coff + 4 * q;
        float4 f0 = *(const float4*)(g_v + b0);
        float4 f1 = *(const float4*)(g_v + b0 + C);
        uint4 hw, lw;
        float a0 = bf16val(f0.x), b0v = bf16val(f1.x);
        float a1 = bf16val(f0.y), b1v = bf16val(f1.y);
        float a2 = bf16val(f0.z), b2v = bf16val(f1.z);
        float a3 = bf16val(f0.w), b3v = bf16val(f1.w);
        hw.x = bf16pair(f0.x, f1.x);
        hw.y = bf16pair(f0.y, f1.y);
        hw.z = bf16pair(f0.z, f1.z);
        hw.w = bf16pair(f0.w, f1.w);
        lw.x = bf16pair(f0.x - a0, f1.x - b0v);
        lw.y = bf16pair(f0.y - a1, f1.y - b1v);
        lw.z = bf16pair(f0.z - a2, f1.z - b2v);
        lw.w = bf16pair(f0.w - a3, f1.w - b3v);
        *(uint4*)(Vph + m * VS + 4 * q) = hw;
        *(uint4*)(Vpl + m * VS + 4 * q) = lw;
    }

    // --- Q (scaled) registers, bf16 hi/lo pairs (warp owns 16 rows) ---
    int jb = w * 16;
    int j1 = jb + g, j2 = jb + 8 + g;
    uint32_t qh[2][4], ql[2][4];
    #pragma unroll
    for (int ks = 0; ks < 2; ks++) {
        int d0 = 2 * (ks * 8 + t), d1 = 2 * (ks * 8 + t + 4);
        float2 qa = *(const float2*)(g_q + (gbase + j1) * C + coff + d0);
        float2 qb = *(const float2*)(g_q + (gbase + j2) * C + coff + d0);
        float2 qc = *(const float2*)(g_q + (gbase + j1) * C + coff + d1);
        float2 qd = *(const float2*)(g_q + (gbase + j2) * C + coff + d1);
        qa.x *= sc; qa.y *= sc; qb.x *= sc; qb.y *= sc;
        qc.x *= sc; qc.y *= sc; qd.x *= sc; qd.y *= sc;
        float a0 = bf16val(qa.x), a1 = bf16val(qa.y);
        float b0 = bf16val(qb.x), b1 = bf16val(qb.y);
        float c0 = bf16val(qc.x), c1 = bf16val(qc.y);
        float e0 = bf16val(qd.x), e1 = bf16val(qd.y);
        qh[ks][0] = bf16pair(qa.x, qa.y);
        qh[ks][1] = bf16pair(qb.x, qb.y);
        qh[ks][2] = bf16pair(qc.x, qc.y);
        qh[ks][3] = bf16pair(qd.x, qd.y);
        ql[ks][0] = bf16pair(qa.x - a0, qa.y - a1);
        ql[ks][1] = bf16pair(qb.x - b0, qb.y - b1);
        ql[ks][2] = bf16pair(qc.x - c0, qc.y - c1);
        ql[ks][3] = bf16pair(qd.x - e0, qd.y - e1);
    }
    __syncthreads();

    float o[4][4];
    #pragma unroll
    for (int nb = 0; nb < 4; nb++)
        #pragma unroll
        for (int r = 0; r < 4; r++) o[nb][r] = 0.0f;
    float lA = 0.f, lB = 0.f;

    const float* bth = g_bt + (size_t)h * NT;

    for (int ch = 0; ch < 8; ch++) {
        int tok0 = ch * 32;
        // ---- S = Q K^T (bf16-3x) ----
        float s[4][4];
        #pragma unroll
        for (int nt = 0; nt < 4; nt++)
            #pragma unroll
            for (int r = 0; r < 4; r++) s[nt][r] = 0.0f;
        #pragma unroll
        for (int nt = 0; nt < 4; nt++) {
            int tokn = tok0 + nt * 8 + g;
            #pragma unroll
            for (int ks = 0; ks < 2; ks++) {
                uint32_t bh2[2], bl2[2];
                const uint32_t* kh = Kh + tokn * KP + ks * 8;
                const uint32_t* kl = Kl + tokn * KP + ks * 8;
                bh2[0] = kh[t]; bh2[1] = kh[t + 4];
                bl2[0] = kl[t]; bl2[1] = kl[t + 4];
                mma_bf16(s[nt], qh[ks], bh2);
                mma_bf16(s[nt], qh[ks], bl2);
                mma_bf16(s[nt], ql[ks], bh2);
            }
        }
        // ---- bias + exp (P stays in registers) ----
        #pragma unroll
        for (int nt = 0; nt < 4; nt++) {
            int k0 = tok0 + nt * 8 + 2 * t;
            float b00 = bth[(size_t)k0 * N + j1];
            float b01 = bth[(size_t)(k0 + 1) * N + j1];
            float b10 = bth[(size_t)k0 * N + j2];
            float b11 = bth[(size_t)(k0 + 1) * N + j2];
            s[nt][0] = __expf(s[nt][0] + b00);
            s[nt][1] = __expf(s[nt][1] + b01);
            s[nt][2] = __expf(s[nt][2] + b10);
            s[nt][3] = __expf(s[nt][3] + b11);
            lA += s[nt][0] + s[nt][1];
            lB += s[nt][2] + s[nt][3];
        }
        // ---- pack P into bf16 hi/lo A-fragments ----
        uint32_t aPh[2][4], aPl[2][4];
        #pragma unroll
        for (int kt = 0; kt < 2; kt++) {
            const float* p0 = s[2 * kt];
            const float* p1 = s[2 * kt + 1];
            float r00 = p0[0] - bf16val(p0[0]), r01 = p0[1] - bf16val(p0[1]);
            float r02 = p0[2] - bf16val(p0[2]), r03 = p0[3] - bf16val(p0[3]);
            float r10 = p1[0] - bf16val(p1[0]), r11 = p1[1] - bf16val(p1[1]);
            float r12 = p1[2] - bf16val(p1[2]), r13 = p1[3] - bf16val(p1[3]);
            aPh[kt][0] = bf16pair(p0[0], p0[1]);
            aPh[kt][1] = bf16pair(p0[2], p0[3]);
            aPh[kt][2] = bf16pair(p1[0], p1[1]);
            aPh[kt][3] = bf16pair(p1[2], p1[3]);
            aPl[kt][0] = bf16pair(r00, r01);
            aPl[kt][1] = bf16pair(r02, r03);
            aPl[kt][2] = bf16pair(r10, r11);
            aPl[kt][3] = bf16pair(r12, r13);
        }
        // ---- O += P V (bf16-3x) ----
        int tp0 = tok0 >> 1;
        #pragma unroll
        for (int kt = 0; kt < 2; kt++) {
            #pragma unroll
            for (int nb = 0; nb < 4; nb++) {
                const uint32_t* vph = Vph + (tp0 + kt * 8 + t) * VS + nb * 8 + g;
                const uint32_t* vpl = Vpl + (tp0 + kt * 8 + t) * VS + nb * 8 + g;
                uint32_t vh[2], vl[2];
                vh[0] = vph[0]; vh[1] = vph[4 * VS];
                vl[0] = vpl[0]; vl[1] = vpl[4 * VS];
                mma_bf16(o[nb], aPh[kt], vh);
                mma_bf16(o[nb], aPh[kt], vl);
                mma_bf16(o[nb], aPl[kt], vh);
            }
        }
    }

    // ---- normalize, gate, store ----
    lA += __shfl_xor_sync(0xffffffffu, lA, 1);
    lA += __shfl_xor_sync(0xffffffffu, lA, 2);
    lB += __shfl_xor_sync(0xffffffffu, lB, 1);
    lB += __shfl_xor_sync(0xffffffffu, lB, 2);
    float inv1 = 1.0f / lA, inv2 = 1.0f / lB;
    #pragma unroll
    for (int nb = 0; nb < 4; nb++) {
        int d = nb * 8 + 2 * t;
        float2 g1 = *(const float2*)(g_g + (gbase + j1) * C + coff + d);
        float2 g2 = *(const float2*)(g_g + (gbase + j2) * C + coff + d);
        float2 o1, o2;
        o1.x = g1.x * o[nb][0] * inv1;
        o1.y = g1.y * o[nb][1] * inv1;
        o2.x = g2.x * o[nb][2] * inv2;
        o2.y = g2.y * o[nb][3] * inv2;
        *(float2*)(g_o + (gbase + j1) * C + coff + d) = o1;
        *(float2*)(g_o + (gbase + j2) * C + coff + d) = o2;
    }
}

extern "C" void kernel_launch(void* const* d_in, const int* in_sizes, int n_in,
                              void* d_out, int out_size) {
    const float* z     = (const float*)d_in[0];
    const float* gamma = (const float*)d_in[1];
    const float* beta  = (const float*)d_in[2];
    const float* Wq    = (const float*)d_in[3];
    const float* Wk    = (const float*)d_in[4];
    const float* Wv    = (const float*)d_in[5];
    const float* Wb    = (const float*)d_in[6];
    const float* Wg    = (const float*)d_in[7];
    const float* Wout  = (const float*)d_in[8];
    float* out = (float*)d_out;

    void *p_lnz, *p_q, *p_k, *p_v, *p_g, *p_o;
    cudaGetSymbolAddress(&p_lnz, g_lnz);
    cudaGetSymbolAddress(&p_q, g_q);
    cudaGetSymbolAddress(&p_k, g_k);
    cudaGetSymbolAddress(&p_v, g_v);
    cudaGetSymbolAddress(&p_g, g_g);
    cudaGetSymbolAddress(&p_o, g_o);

    cudaFuncSetAttribute(gemm_fused,
                         cudaFuncAttributeMaxDynamicSharedMemorySize, GEMM_SMEM);
    cudaFuncSetAttribute(attn_mma,
                         cudaFuncAttributeMaxDynamicSharedMemorySize, ATTN_SMEM);

    ln_kernel<<<NT / 8, 256>>>(z, gamma, beta, Wb);
    W5 ws; ws.w[0] = Wq; ws.w[1] = Wk; ws.w[2] = Wv; ws.w[3] = Wg; ws.w[4] = Wout;
    wprep_kernel<<<dim3(32, 5), 256>>>(ws);

    Y4 yq; yq.p[0] = (float*)p_q; yq.p[1] = (float*)p_k;
    yq.p[2] = (float*)p_v; yq.p[3] = (float*)p_g;
    gemm_fused<<<NT / 128, GT, GEMM_SMEM>>>((const float*)p_lnz, 0, 4, yq, 0x8);

    attn_mma<<<dim3(N, H), AT, ATTN_SMEM>>>();

    Y4 yo; yo.p[0] = out; yo.p[1] = yo.p[2] = yo.p[3] = nullptr;
    gemm_fused<<<NT / 128, GT, GEMM_SMEM>>>((const float*)p_o, 4, 1, yo, 0);
}

// round 12
// speedup vs baseline: 1.3287x; 1.0148x over previous
#include <cuda_runtime.h>
#include <cuda_bf16.h>
#include <math.h>
#include <stdint.h>

#define N 256
#define NT (N*N)
#define C 128
#define H 4
#define D 32

// -------- scratch (device globals; no allocation allowed) --------
__device__ float    g_lnz[NT*C];
__device__ float    g_q[NT*C];
__device__ float    g_k[NT*C];
__device__ float    g_v[NT*C];
__device__ float    g_g[NT*C];     // sigmoid(z@Wg)
__device__ float    g_bt[H*NT];    // bias*log2e: [h][j][k]
__device__ float    g_o[NT*C];     // gated attention output
__device__ uint32_t g_wph[5*C*(C/2)];
__device__ uint32_t g_wpl[5*C*(C/2)];

struct Y4 { float* p[4]; };
struct W5 { const float* w[5]; };

// ---------- helpers ----------
__device__ __forceinline__ float bf16val(float x) {
    return __bfloat162float(__float2bfloat16(x));
}
__device__ __forceinline__ uint32_t bf16pair(float even, float odd) {
    uint32_t r;
    asm("cvt.rn.satfinite.bf16x2.f32 %0, %1, %2;" : "=r"(r) : "f"(odd), "f"(even));
    return r;
}
// truncation split: hi = top 16 bits (exact bf16), lo = x - hi (exact)
__device__ __forceinline__ float trunc_hi(float x) {
    return __uint_as_float(__float_as_uint(x) & 0xFFFF0000u);
}
__device__ __forceinline__ uint32_t hipack(float a, float b) {
    return __byte_perm(__float_as_uint(a), __float_as_uint(b), 0x7632);
}
__device__ __forceinline__ float ex2f(float x) {
    float y;
    asm("ex2.approx.f32 %0, %1;" : "=f"(y) : "f"(x));
    return y;
}
__device__ __forceinline__ void mma_bf16(float* c, const uint32_t* a,
                                         const uint32_t* b) {
    asm volatile(
        "mma.sync.aligned.m16n8k16.row.col.f32.bf16.bf16.f32 "
        "{%0,%1,%2,%3},{%4,%5,%6,%7},{%8,%9},{%0,%1,%2,%3};"
        : "+f"(c[0]), "+f"(c[1]), "+f"(c[2]), "+f"(c[3])
        : "r"(a[0]), "r"(a[1]), "r"(a[2]), "r"(a[3]), "r"(b[0]), "r"(b[1]));
}
__device__ __forceinline__ void cp16(uint32_t* smem_dst, const void* gsrc) {
    uint32_t s = (uint32_t)__cvta_generic_to_shared(smem_dst);
    asm volatile("cp.async.cg.shared.global [%0], [%1], 16;\n"
                 :: "r"(s), "l"(gsrc));
}

#define LOG2E 1.4426950408889634f

// ---------------- LayerNorm + fused bias projection ----------------
__global__ void ln_kernel(const float* __restrict__ z,
                          const float* __restrict__ gamma,
                          const float* __restrict__ beta,
                          const float* __restrict__ Wb) {
    int warp = threadIdx.x >> 5, lane = threadIdx.x & 31;
    int t = blockIdx.x * 8 + warp;
    const float4 v = *(const float4*)(z + (size_t)t * C + lane * 4);
    float s = v.x + v.y + v.z + v.w;
    #pragma unroll
    for (int o = 16; o; o >>= 1) s += __shfl_xor_sync(0xffffffffu, s, o);
    float mu = s * (1.0f / C);
    float d0 = v.x - mu, d1 = v.y - mu, d2 = v.z - mu, d3 = v.w - mu;
    float vs = d0*d0 + d1*d1 + d2*d2 + d3*d3;
    #pragma unroll
    for (int o = 16; o; o >>= 1) vs += __shfl_xor_sync(0xffffffffu, vs, o);
    float r = rsqrtf(vs * (1.0f / C) + 1e-5f);
    float4 gm = *(const float4*)(gamma + lane * 4);
    float4 bt = *(const float4*)(beta + lane * 4);
    float4 out;
    out.x = d0 * r * gm.x + bt.x;
    out.y = d1 * r * gm.y + bt.y;
    out.z = d2 * r * gm.z + bt.z;
    out.w = d3 * r * gm.w + bt.w;
    *(float4*)(g_lnz + (size_t)t * C + lane * 4) = out;

    float4 w0 = *(const float4*)(Wb + lane * 16);
    float4 w1 = *(const float4*)(Wb + lane * 16 + 4);
    float4 w2 = *(const float4*)(Wb + lane * 16 + 8);
    float4 w3 = *(const float4*)(Wb + lane * 16 + 12);
    float4 p;
    p.x = out.x * w0.x + out.y * w1.x + out.z * w2.x + out.w * w3.x;
    p.y = out.x * w0.y + out.y * w1.y + out.z * w2.y + out.w * w3.y;
    p.z = out.x * w0.z + out.y * w1.z + out.z * w2.z + out.w * w3.z;
    p.w = out.x * w0.w + out.y * w1.w + out.z * w2.w + out.w * w3.w;
    #pragma unroll
    for (int o = 16; o; o >>= 1) {
        p.x += __shfl_xor_sync(0xffffffffu, p.x, o);
        p.y += __shfl_xor_sync(0xffffffffu, p.y, o);
        p.z += __shfl_xor_sync(0xffffffffu, p.z, o);
        p.w += __shfl_xor_sync(0xffffffffu, p.w, o);
    }
    if (lane == 0) {
        // token t = (j, k); store bias*log2e at [h][j][k]
        int j = t >> 8, k = t & 255;
        size_t o2 = (size_t)j * N + k;
        g_bt[0 * NT + o2] = p.x * LOG2E;
        g_bt[1 * NT + o2] = p.y * LOG2E;
        g_bt[2 * NT + o2] = p.z * LOG2E;
        g_bt[3 * NT + o2] = p.w * LOG2E;
    }
}

// ------- weight prep: split + pack + transpose -------
__global__ void wprep_kernel(W5 ws) {
    int mat = blockIdx.y;
    int idx = blockIdx.x * 256 + threadIdx.x;
    int n = idx >> 6, k2 = idx & 63;
    const float* W = ws.w[mat];
    float w0 = W[(2 * k2) * C + n];
    float w1 = W[(2 * k2 + 1) * C + n];
    float h0 = trunc_hi(w0), h1 = trunc_hi(w1);
    g_wph[mat * 8192 + n * 64 + k2] = hipack(w0, w1);
    g_wpl[mat * 8192 + n * 64 + k2] = bf16pair(w0 - h0, w1 - h1);
}

// ---------------- fused bf16-3x GEMM: 512 threads, 16 warps ----------------
#define XW 68
#define XPLANE (128 * XW)
#define WBUF (2 * XPLANE)
#define GEMM_SMEM ((2 * XPLANE + 2 * WBUF) * 4)
#define GT 512

__global__ void __launch_bounds__(GT, 1)
gemm_fused(const float* __restrict__ X, int slot0, int nmat, Y4 ys, int sigmask) {
    extern __shared__ uint32_t sm4[];
    uint32_t* Xh2 = sm4;
    uint32_t* Xl2 = sm4 + XPLANE;
    uint32_t* Wb  = sm4 + 2 * XPLANE;

    int tid = threadIdx.x;
    int warp = tid >> 5, lane = tid & 31;
    int g = lane >> 2, t = lane & 3;
    int wm = warp >> 2, wn = warp & 3;
    int row0 = blockIdx.x * 128;

    auto issueW = [&](int s, int buf) {
        uint32_t* wb = Wb + buf * WBUF;
        #pragma unroll
        for (int i = 0; i < 8; i++) {
            int id = tid + i * GT;
            int plane = id >> 11, r = id & 2047;
            int n = r >> 4, q = r & 15;
            const uint32_t* src =
                (plane ? g_wpl : g_wph) + (slot0 + s) * 8192 + n * 64 + q * 4;
            cp16(wb + plane * XPLANE + n * XW + q * 4, src);
        }
    };

    issueW(0, 0);
    asm volatile("cp.async.commit_group;\n");
    #pragma unroll
    for (int i = 0; i < 8; i++) {
        int id = tid + i * GT;
        int row = id >> 5, c4 = id & 31;
        float4 v = *(const float4*)(X + (size_t)(row0 + row) * C + c4 * 4);
        float h0 = trunc_hi(v.x), h1 = trunc_hi(v.y);
        float h2 = trunc_hi(v.z), h3 = trunc_hi(v.w);
        uint32_t* xh = Xh2 + row * XW + c4 * 2;
        uint32_t* xl = Xl2 + row * XW + c4 * 2;
        xh[0] = hipack(v.x, v.y);
        xh[1] = hipack(v.z, v.w);
        xl[0] = bf16pair(v.x - h0, v.y - h1);
        xl[1] = bf16pair(v.z - h2, v.w - h3);
    }

    #pragma unroll 1
    for (int s = 0; s < nmat; s++) {
        if (s + 1 < nmat) {
            issueW(s + 1, (s + 1) & 1);
            asm volatile("cp.async.commit_group;\n");
            asm volatile("cp.async.wait_group 1;\n");
        } else {
            asm volatile("cp.async.wait_group 0;\n");
        }
        __syncthreads();

        uint32_t* Wh2 = Wb + (s & 1) * WBUF;
        uint32_t* Wl2 = Wh2 + XPLANE;

        float c[2][4][4];
        #pragma unroll
        for (int mb = 0; mb < 2; mb++)
            #pragma unroll
            for (int nb = 0; nb < 4; nb++)
                #pragma unroll
                for (int r = 0; r < 4; r++) c[mb][nb][r] = 0.0f;

        #pragma unroll
        for (int ks = 0; ks < 8; ks++) {
            int kb = ks * 8;
            uint32_t bh[4][2], bl[4][2];
            #pragma unroll
            for (int nb = 0; nb < 4; nb++) {
                int n = wn * 32 + nb * 8 + g;
                bh[nb][0] = Wh2[n * XW + kb + t];
                bh[nb][1] = Wh2[n * XW + kb + t + 4];
                bl[nb][0] = Wl2[n * XW + kb + t];
                bl[nb][1] = Wl2[n * XW + kb + t + 4];
            }
            #pragma unroll
            for (int mb = 0; mb < 2; mb++) {
                int r = wm * 32 + mb * 16 + g;
                uint32_t ah[4], al[4];
                ah[0] = Xh2[r * XW + kb + t];
                ah[1] = Xh2[(r + 8) * XW + kb + t];
                ah[2] = Xh2[r * XW + kb + t + 4];
                ah[3] = Xh2[(r + 8) * XW + kb + t + 4];
                al[0] = Xl2[r * XW + kb + t];
                al[1] = Xl2[(r + 8) * XW + kb + t];
                al[2] = Xl2[r * XW + kb + t + 4];
                al[3] = Xl2[(r + 8) * XW + kb + t + 4];
                #pragma unroll
                for (int nb = 0; nb < 4; nb++) {
                    mma_bf16(c[mb][nb], ah, bh[nb]);
                    mma_bf16(c[mb][nb], ah, bl[nb]);
                    mma_bf16(c[mb][nb], al, bh[nb]);
                }
            }
        }

        float* Y = ys.p[s];
        int sg = (sigmask >> s) & 1;
        #pragma unroll
        for (int mb = 0; mb < 2; mb++) {
            int r0 = row0 + wm * 32 + mb * 16 + g;
            #pragma unroll
            for (int nb = 0; nb < 4; nb++) {
                int col = wn * 32 + nb * 8 + 2 * t;
                float v0 = c[mb][nb][0], v1 = c[mb][nb][1];
                float v2 = c[mb][nb][2], v3 = c[mb][nb][3];
                if (sg) {
                    v0 = 1.0f / (1.0f + __expf(-v0));
                    v1 = 1.0f / (1.0f + __expf(-v1));
                    v2 = 1.0f / (1.0f + __expf(-v2));
                    v3 = 1.0f / (1.0f + __expf(-v3));
                }
                *(float2*)(Y + (size_t)r0 * C + col) = make_float2(v0, v1);
                *(float2*)(Y + (size_t)(r0 + 8) * C + col) = make_float2(v2, v3);
            }
        }
        __syncthreads();
    }
}

// ---------------- attention: all-bf16-compensated, P in registers ----------------
#define KP 20
#define VS 40
#define KPL (256 * KP)
#define VPL (128 * VS)
#define AT 512
#define ATTN_SMEM ((2 * KPL + 2 * VPL) * 4)   // 81920 B

__global__ void __launch_bounds__(AT, 1)
attn_mma() {
    extern __shared__ uint32_t smu[];
    uint32_t* Kh  = smu;
    uint32_t* Kl  = smu + KPL;
    uint32_t* Vph = smu + 2 * KPL;
    uint32_t* Vpl = Vph + VPL;

    int i = blockIdx.x, h = blockIdx.y;
    int tid = threadIdx.x;
    int w = tid >> 5, lane = tid & 31;
    int g = lane >> 2, t = lane & 3;
    int coff = h * D;
    size_t gbase = (size_t)i * N;
    const float sc2 = 0.17677669529663687f * LOG2E;  // 1/sqrt(32) * log2(e)

    // --- stage K: pairs along d (hi/lo, truncation split) ---
    #pragma unroll
    for (int it = 0; it < 4; it++) {
        int idx = tid + it * AT;
        int tok = idx >> 3, f = idx & 7;
        float4 kv = *(const float4*)(g_k + (gbase + tok) * C + coff + f * 4);
        float h0 = trunc_hi(kv.x), h1 = trunc_hi(kv.y);
        float h2 = trunc_hi(kv.z), h3 = trunc_hi(kv.w);
        uint32_t* kh = Kh + tok * KP + f * 2;
        uint32_t* kl = Kl + tok * KP + f * 2;
        kh[0] = hipack(kv.x, kv.y);
        kh[1] = hipack(kv.z, kv.w);
        kl[0] = bf16pair(kv.x - h0, kv.y - h1);
        kl[1] = bf16pair(kv.z - h2, kv.w - h3);
    }
    // --- stage V: pairs along tokens (hi/lo, truncation split) ---
    #pragma unroll
    for (int it = 0; it < 2; it++) {
        int idx = tid + it * AT;
        int m = idx >> 3, q = idx & 7;
        size_t b0 = (gbase + 2 * m) * C + coff + 4 * q;
        float4 f0 = *(const float4*)(g_v + b0);
        float4 f1 = *(const float4*)(g_v + b0 + C);
        uint4 hw, lw;
        float a0 = trunc_hi(f0.x), b0v = trunc_hi(f1.x);
        float a1 = trunc_hi(f0.y), b1v = trunc_hi(f1.y);
        float a2 = trunc_hi(f0.z), b2v = trunc_hi(f1.z);
        float a3 = trunc_hi(f0.w), b3v = trunc_hi(f1.w);
        hw.x = hipack(f0.x, f1.x);
        hw.y = hipack(f0.y, f1.y);
        hw.z = hipack(f0.z, f1.z);
        hw.w = hipack(f0.w, f1.w);
        lw.x = bf16pair(f0.x - a0, f1.x - b0v);
        lw.y = bf16pair(f0.y - a1, f1.y - b1v);
        lw.z = bf16pair(f0.z - a2, f1.z - b2v);
        lw.w = bf16pair(f0.w - a3, f1.w - b3v);
        *(uint4*)(Vph + m * VS + 4 * q) = hw;
        *(uint4*)(Vpl + m * VS + 4 * q) = lw;
    }

    // --- Q (scaled by sc*log2e) registers, hi/lo pairs ---
    int jb = w * 16;
    int j1 = jb + g, j2 = jb + 8 + g;
    uint32_t qh[2][4], ql[2][4];
    #pragma unroll
    for (int ks = 0; ks < 2; ks++) {
        int d0 = 2 * (ks * 8 + t), d1 = 2 * (ks * 8 + t + 4);
        float2 qa = *(const float2*)(g_q + (gbase + j1) * C + coff + d0);
        float2 qb = *(const float2*)(g_q + (gbase + j2) * C + coff + d0);
        float2 qc = *(const float2*)(g_q + (gbase + j1) * C + coff + d1);
        float2 qd = *(const float2*)(g_q + (gbase + j2) * C + coff + d1);
        qa.x *= sc2; qa.y *= sc2; qb.x *= sc2; qb.y *= sc2;
        qc.x *= sc2; qc.y *= sc2; qd.x *= sc2; qd.y *= sc2;
        float a0 = trunc_hi(qa.x), a1 = trunc_hi(qa.y);
        float b0 = trunc_hi(qb.x), b1 = trunc_hi(qb.y);
        float c0 = trunc_hi(qc.x), c1 = trunc_hi(qc.y);
        float e0 = trunc_hi(qd.x), e1 = trunc_hi(qd.y);
        qh[ks][0] = hipack(qa.x, qa.y);
        qh[ks][1] = hipack(qb.x, qb.y);
        qh[ks][2] = hipack(qc.x, qc.y);
        qh[ks][3] = hipack(qd.x, qd.y);
        ql[ks][0] = bf16pair(qa.x - a0, qa.y - a1);
        ql[ks][1] = bf16pair(qb.x - b0, qb.y - b1);
        ql[ks][2] = bf16pair(qc.x - c0, qc.y - c1);
        ql[ks][3] = bf16pair(qd.x - e0, qd.y - e1);
    }
    __syncthreads();

    float o[4][4];
    #pragma unroll
    for (int nb = 0; nb < 4; nb++)
        #pragma unroll
        for (int r = 0; r < 4; r++) o[nb][r] = 0.0f;
    float lA = 0.f, lB = 0.f;

    const float* bj1 = g_bt + (size_t)h * NT + (size_t)j1 * N;
    const float* bj2 = g_bt + (size_t)h * NT + (size_t)j2 * N;

    for (int ch = 0; ch < 8; ch++) {
        int tok0 = ch * 32;
        // ---- S = Q K^T (bf16-3x) ----
        float s[4][4];
        #pragma unroll
        for (int nt = 0; nt < 4; nt++)
            #pragma unroll
            for (int r = 0; r < 4; r++) s[nt][r] = 0.0f;
        #pragma unroll
        for (int nt = 0; nt < 4; nt++) {
            int tokn = tok0 + nt * 8 + g;
            #pragma unroll
            for (int ks = 0; ks < 2; ks++) {
                uint32_t bh2[2], bl2[2];
                const uint32_t* kh = Kh + tokn * KP + ks * 8;
                const uint32_t* kl = Kl + tokn * KP + ks * 8;
                bh2[0] = kh[t]; bh2[1] = kh[t + 4];
                bl2[0] = kl[t]; bl2[1] = kl[t + 4];
                mma_bf16(s[nt], qh[ks], bh2);
                mma_bf16(s[nt], qh[ks], bl2);
                mma_bf16(s[nt], ql[ks], bh2);
            }
        }
        // ---- bias + ex2 (P stays in registers) ----
        #pragma unroll
        for (int nt = 0; nt < 4; nt++) {
            int k0 = tok0 + nt * 8 + 2 * t;
            float2 ba = *(const float2*)(bj1 + k0);
            float2 bb = *(const float2*)(bj2 + k0);
            s[nt][0] = ex2f(s[nt][0] + ba.x);
            s[nt][1] = ex2f(s[nt][1] + ba.y);
            s[nt][2] = ex2f(s[nt][2] + bb.x);
            s[nt][3] = ex2f(s[nt][3] + bb.y);
            lA += s[nt][0] + s[nt][1];
            lB += s[nt][2] + s[nt][3];
        }
        // ---- pack P into bf16 hi/lo A-fragments (truncation split) ----
        uint32_t aPh[2][4], aPl[2][4];
        #pragma unroll
        for (int kt = 0; kt < 2; kt++) {
            const float* p0 = s[2 * kt];
            const float* p1 = s[2 * kt + 1];
            float r00 = p0[0] - trunc_hi(p0[0]), r01 = p0[1] - trunc_hi(p0[1]);
            float r02 = p0[2] - trunc_hi(p0[2]), r03 = p0[3] - trunc_hi(p0[3]);
            float r10 = p1[0] - trunc_hi(p1[0]), r11 = p1[1] - trunc_hi(p1[1]);
            float r12 = p1[2] - trunc_hi(p1[2]), r13 = p1[3] - trunc_hi(p1[3]);
            aPh[kt][0] = hipack(p0[0], p0[1]);
            aPh[kt][1] = hipack(p0[2], p0[3]);
            aPh[kt][2] = hipack(p1[0], p1[1]);
            aPh[kt][3] = hipack(p1[2], p1[3]);
            aPl[kt][0] = bf16pair(r00, r01);
            aPl[kt][1] = bf16pair(r02, r03);
            aPl[kt][2] = bf16pair(r10, r11);
            aPl[kt][3] = bf16pair(r12, r13);
        }
        // ---- O += P V (bf16-3x) ----
        int tp0 = tok0 >> 1;
        #pragma unroll
        for (int kt = 0; kt < 2; kt++) {
            #pragma unroll
            for (int nb = 0; nb < 4; nb++) {
                const uint32_t* vph = Vph + (tp0 + kt * 8 + t) * VS + nb * 8 + g;
                const uint32_t* vpl = Vpl + (tp0 + kt * 8 + t) * VS + nb * 8 + g;
                uint32_t vh[2], vl[2];
                vh[0] = vph[0]; vh[1] = vph[4 * VS];
                vl[0] = vpl[0]; vl[1] = vpl[4 * VS];
                mma_bf16(o[nb], aPh[kt], vh);
                mma_bf16(o[nb], aPh[kt], vl);
                mma_bf16(o[nb], aPl[kt], vh);
            }
        }
    }

    // ---- normalize, gate, store ----
    lA += __shfl_xor_sync(0xffffffffu, lA, 1);
    lA += __shfl_xor_sync(0xffffffffu, lA, 2);
    lB += __shfl_xor_sync(0xffffffffu, lB, 1);
    lB += __shfl_xor_sync(0xffffffffu, lB, 2);
    float inv1 = 1.0f / lA, inv2 = 1.0f / lB;
    #pragma unroll
    for (int nb = 0; nb < 4; nb++) {
        int d = nb * 8 + 2 * t;
        float2 g1 = *(const float2*)(g_g + (gbase + j1) * C + coff + d);
        float2 g2 = *(const float2*)(g_g + (gbase + j2) * C + coff + d);
        float2 o1, o2;
        o1.x = g1.x * o[nb][0] * inv1;
        o1.y = g1.y * o[nb][1] * inv1;
        o2.x = g2.x * o[nb][2] * inv2;
        o2.y = g2.y * o[nb][3] * inv2;
        *(float2*)(g_o + (gbase + j1) * C + coff + d) = o1;
        *(float2*)(g_o + (gbase + j2) * C + coff + d) = o2;
    }
}

extern "C" void kernel_launch(void* const* d_in, const int* in_sizes, int n_in,
                              void* d_out, int out_size) {
    const float* z     = (const float*)d_in[0];
    const float* gamma = (const float*)d_in[1];
    const float* beta  = (const float*)d_in[2];
    const float* Wq    = (const float*)d_in[3];
    const float* Wk    = (const float*)d_in[4];
    const float* Wv    = (const float*)d_in[5];
    const float* Wb    = (const float*)d_in[6];
    const float* Wg    = (const float*)d_in[7];
    const float* Wout  = (const float*)d_in[8];
    float* out = (float*)d_out;

    void *p_lnz, *p_q, *p_k, *p_v, *p_g, *p_o;
    cudaGetSymbolAddress(&p_lnz, g_lnz);
    cudaGetSymbolAddress(&p_q, g_q);
    cudaGetSymbolAddress(&p_k, g_k);
    cudaGetSymbolAddress(&p_v, g_v);
    cudaGetSymbolAddress(&p_g, g_g);
    cudaGetSymbolAddress(&p_o, g_o);

    cudaFuncSetAttribute(gemm_fused,
                         cudaFuncAttributeMaxDynamicSharedMemorySize, GEMM_SMEM);
    cudaFuncSetAttribute(attn_mma,
                         cudaFuncAttributeMaxDynamicSharedMemorySize, ATTN_SMEM);

    ln_kernel<<<NT / 8, 256>>>(z, gamma, beta, Wb);
    W5 ws; ws.w[0] = Wq; ws.w[1] = Wk; ws.w[2] = Wv; ws.w[3] = Wg; ws.w[4] = Wout;
    wprep_kernel<<<dim3(32, 5), 256>>>(ws);

    Y4 yq; yq.p[0] = (float*)p_q; yq.p[1] = (float*)p_k;
    yq.p[2] = (float*)p_v; yq.p[3] = (float*)p_g;
    gemm_fused<<<NT / 128, GT, GEMM_SMEM>>>((const float*)p_lnz, 0, 4, yq, 0x8);

    attn_mma<<<dim3(N, H), AT, ATTN_SMEM>>>();

    Y4 yo; yo.p[0] = out; yo.p[1] = yo.p[2] = yo.p[3] = nullptr;
    gemm_fused<<<NT / 128, GT, GEMM_SMEM>>>((const float*)p_o, 4, 1, yo, 0);
}

// round 13
// speedup vs baseline: 1.4557x; 1.0956x over previous
#include <cuda_runtime.h>
#include <cuda_bf16.h>
#include <math.h>
#include <stdint.h>

#define N 256
#define NT (N*N)
#define C 128
#define H 4
#define D 32

// -------- scratch (device globals; no allocation allowed) --------
__device__ float    g_lnz[NT*C];
__device__ float    g_q[NT*C];
__device__ float    g_k[NT*C];
__device__ float    g_v[NT*C];
__device__ float    g_g[NT*C];     // sigmoid(z@Wg)
__device__ float    g_bt[H*NT];    // bias*log2e: [h][j][k]
__device__ float    g_o[NT*C];     // gated attention output
__device__ uint32_t g_wph[5*C*(C/2)];
__device__ uint32_t g_wpl[5*C*(C/2)];

struct Y4 { float* p[4]; };
struct W5 { const float* w[5]; };

// ---------- helpers ----------
__device__ __forceinline__ uint32_t bf16pair(float even, float odd) {
    uint32_t r;
    asm("cvt.rn.satfinite.bf16x2.f32 %0, %1, %2;" : "=r"(r) : "f"(odd), "f"(even));
    return r;
}
__device__ __forceinline__ float trunc_hi(float x) {
    return __uint_as_float(__float_as_uint(x) & 0xFFFF0000u);
}
__device__ __forceinline__ uint32_t hipack(float a, float b) {
    return __byte_perm(__float_as_uint(a), __float_as_uint(b), 0x7632);
}
__device__ __forceinline__ float ex2f(float x) {
    float y;
    asm("ex2.approx.f32 %0, %1;" : "=f"(y) : "f"(x));
    return y;
}
__device__ __forceinline__ void mma_bf16(float* c, const uint32_t* a,
                                         const uint32_t* b) {
    asm volatile(
        "mma.sync.aligned.m16n8k16.row.col.f32.bf16.bf16.f32 "
        "{%0,%1,%2,%3},{%4,%5,%6,%7},{%8,%9},{%0,%1,%2,%3};"
        : "+f"(c[0]), "+f"(c[1]), "+f"(c[2]), "+f"(c[3])
        : "r"(a[0]), "r"(a[1]), "r"(a[2]), "r"(a[3]), "r"(b[0]), "r"(b[1]));
}
__device__ __forceinline__ void cp16(uint32_t* smem_dst, const void* gsrc) {
    uint32_t s = (uint32_t)__cvta_generic_to_shared(smem_dst);
    asm volatile("cp.async.cg.shared.global [%0], [%1], 16;\n"
                 :: "r"(s), "l"(gsrc));
}

#define LOG2E 1.4426950408889634f

// ---------------- LayerNorm + fused bias projection ----------------
__global__ void ln_kernel(const float* __restrict__ z,
                          const float* __restrict__ gamma,
                          const float* __restrict__ beta,
                          const float* __restrict__ Wb) {
    int warp = threadIdx.x >> 5, lane = threadIdx.x & 31;
    int t = blockIdx.x * 8 + warp;
    const float4 v = *(const float4*)(z + (size_t)t * C + lane * 4);
    float s = v.x + v.y + v.z + v.w;
    #pragma unroll
    for (int o = 16; o; o >>= 1) s += __shfl_xor_sync(0xffffffffu, s, o);
    float mu = s * (1.0f / C);
    float d0 = v.x - mu, d1 = v.y - mu, d2 = v.z - mu, d3 = v.w - mu;
    float vs = d0*d0 + d1*d1 + d2*d2 + d3*d3;
    #pragma unroll
    for (int o = 16; o; o >>= 1) vs += __shfl_xor_sync(0xffffffffu, vs, o);
    float r = rsqrtf(vs * (1.0f / C) + 1e-5f);
    float4 gm = *(const float4*)(gamma + lane * 4);
    float4 bt = *(const float4*)(beta + lane * 4);
    float4 out;
    out.x = d0 * r * gm.x + bt.x;
    out.y = d1 * r * gm.y + bt.y;
    out.z = d2 * r * gm.z + bt.z;
    out.w = d3 * r * gm.w + bt.w;
    *(float4*)(g_lnz + (size_t)t * C + lane * 4) = out;

    float4 w0 = *(const float4*)(Wb + lane * 16);
    float4 w1 = *(const float4*)(Wb + lane * 16 + 4);
    float4 w2 = *(const float4*)(Wb + lane * 16 + 8);
    float4 w3 = *(const float4*)(Wb + lane * 16 + 12);
    float4 p;
    p.x = out.x * w0.x + out.y * w1.x + out.z * w2.x + out.w * w3.x;
    p.y = out.x * w0.y + out.y * w1.y + out.z * w2.y + out.w * w3.y;
    p.z = out.x * w0.z + out.y * w1.z + out.z * w2.z + out.w * w3.z;
    p.w = out.x * w0.w + out.y * w1.w + out.z * w2.w + out.w * w3.w;
    #pragma unroll
    for (int o = 16; o; o >>= 1) {
        p.x += __shfl_xor_sync(0xffffffffu, p.x, o);
        p.y += __shfl_xor_sync(0xffffffffu, p.y, o);
        p.z += __shfl_xor_sync(0xffffffffu, p.z, o);
        p.w += __shfl_xor_sync(0xffffffffu, p.w, o);
    }
    if (lane == 0) {
        int j = t >> 8, k = t & 255;
        size_t o2 = (size_t)j * N + k;
        g_bt[0 * NT + o2] = p.x * LOG2E;
        g_bt[1 * NT + o2] = p.y * LOG2E;
        g_bt[2 * NT + o2] = p.z * LOG2E;
        g_bt[3 * NT + o2] = p.w * LOG2E;
    }
}

// ------- weight prep: split + pack + transpose -------
__global__ void wprep_kernel(W5 ws) {
    int mat = blockIdx.y;
    int idx = blockIdx.x * 256 + threadIdx.x;
    int n = idx >> 6, k2 = idx & 63;
    const float* W = ws.w[mat];
    float w0 = W[(2 * k2) * C + n];
    float w1 = W[(2 * k2 + 1) * C + n];
    float h0 = trunc_hi(w0), h1 = trunc_hi(w1);
    g_wph[mat * 8192 + n * 64 + k2] = hipack(w0, w1);
    g_wpl[mat * 8192 + n * 64 + k2] = bf16pair(w0 - h0, w1 - h1);
}

// ---------------- fused bf16-3x GEMM: 512 threads, 16 warps (unchanged) ----------------
#define XW 68
#define XPLANE (128 * XW)
#define WBUF (2 * XPLANE)
#define GEMM_SMEM ((2 * XPLANE + 2 * WBUF) * 4)
#define GT 512

__global__ void __launch_bounds__(GT, 1)
gemm_fused(const float* __restrict__ X, int slot0, int nmat, Y4 ys, int sigmask) {
    extern __shared__ uint32_t sm4[];
    uint32_t* Xh2 = sm4;
    uint32_t* Xl2 = sm4 + XPLANE;
    uint32_t* Wb  = sm4 + 2 * XPLANE;

    int tid = threadIdx.x;
    int warp = tid >> 5, lane = tid & 31;
    int g = lane >> 2, t = lane & 3;
    int wm = warp >> 2, wn = warp & 3;
    int row0 = blockIdx.x * 128;

    auto issueW = [&](int s, int buf) {
        uint32_t* wb = Wb + buf * WBUF;
        #pragma unroll
        for (int i = 0; i < 8; i++) {
            int id = tid + i * GT;
            int plane = id >> 11, r = id & 2047;
            int n = r >> 4, q = r & 15;
            const uint32_t* src =
                (plane ? g_wpl : g_wph) + (slot0 + s) * 8192 + n * 64 + q * 4;
            cp16(wb + plane * XPLANE + n * XW + q * 4, src);
        }
    };

    issueW(0, 0);
    asm volatile("cp.async.commit_group;\n");
    #pragma unroll
    for (int i = 0; i < 8; i++) {
        int id = tid + i * GT;
        int row = id >> 5, c4 = id & 31;
        float4 v = *(const float4*)(X + (size_t)(row0 + row) * C + c4 * 4);
        float h0 = trunc_hi(v.x), h1 = trunc_hi(v.y);
        float h2 = trunc_hi(v.z), h3 = trunc_hi(v.w);
        uint32_t* xh = Xh2 + row * XW + c4 * 2;
        uint32_t* xl = Xl2 + row * XW + c4 * 2;
        xh[0] = hipack(v.x, v.y);
        xh[1] = hipack(v.z, v.w);
        xl[0] = bf16pair(v.x - h0, v.y - h1);
        xl[1] = bf16pair(v.z - h2, v.w - h3);
    }

    #pragma unroll 1
    for (int s = 0; s < nmat; s++) {
        if (s + 1 < nmat) {
            issueW(s + 1, (s + 1) & 1);
            asm volatile("cp.async.commit_group;\n");
            asm volatile("cp.async.wait_group 1;\n");
        } else {
            asm volatile("cp.async.wait_group 0;\n");
        }
        __syncthreads();

        uint32_t* Wh2 = Wb + (s & 1) * WBUF;
        uint32_t* Wl2 = Wh2 + XPLANE;

        float c[2][4][4];
        #pragma unroll
        for (int mb = 0; mb < 2; mb++)
            #pragma unroll
            for (int nb = 0; nb < 4; nb++)
                #pragma unroll
                for (int r = 0; r < 4; r++) c[mb][nb][r] = 0.0f;

        #pragma unroll
        for (int ks = 0; ks < 8; ks++) {
            int kb = ks * 8;
            uint32_t bh[4][2], bl[4][2];
            #pragma unroll
            for (int nb = 0; nb < 4; nb++) {
                int n = wn * 32 + nb * 8 + g;
                bh[nb][0] = Wh2[n * XW + kb + t];
                bh[nb][1] = Wh2[n * XW + kb + t + 4];
                bl[nb][0] = Wl2[n * XW + kb + t];
                bl[nb][1] = Wl2[n * XW + kb + t + 4];
            }
            #pragma unroll
            for (int mb = 0; mb < 2; mb++) {
                int r = wm * 32 + mb * 16 + g;
                uint32_t ah[4], al[4];
                ah[0] = Xh2[r * XW + kb + t];
                ah[1] = Xh2[(r + 8) * XW + kb + t];
                ah[2] = Xh2[r * XW + kb + t + 4];
                ah[3] = Xh2[(r + 8) * XW + kb + t + 4];
                al[0] = Xl2[r * XW + kb + t];
                al[1] = Xl2[(r + 8) * XW + kb + t];
                al[2] = Xl2[r * XW + kb + t + 4];
                al[3] = Xl2[(r + 8) * XW + kb + t + 4];
                #pragma unroll
                for (int nb = 0; nb < 4; nb++) {
                    mma_bf16(c[mb][nb], ah, bh[nb]);
                    mma_bf16(c[mb][nb], ah, bl[nb]);
                    mma_bf16(c[mb][nb], al, bh[nb]);
                }
            }
        }

        float* Y = ys.p[s];
        int sg = (sigmask >> s) & 1;
        #pragma unroll
        for (int mb = 0; mb < 2; mb++) {
            int r0 = row0 + wm * 32 + mb * 16 + g;
            #pragma unroll
            for (int nb = 0; nb < 4; nb++) {
                int col = wn * 32 + nb * 8 + 2 * t;
                float v0 = c[mb][nb][0], v1 = c[mb][nb][1];
                float v2 = c[mb][nb][2], v3 = c[mb][nb][3];
                if (sg) {
                    v0 = 1.0f / (1.0f + __expf(-v0));
                    v1 = 1.0f / (1.0f + __expf(-v1));
                    v2 = 1.0f / (1.0f + __expf(-v2));
                    v3 = 1.0f / (1.0f + __expf(-v3));
                }
                *(float2*)(Y + (size_t)r0 * C + col) = make_float2(v0, v1);
                *(float2*)(Y + (size_t)(r0 + 8) * C + col) = make_float2(v2, v3);
            }
        }
        __syncthreads();
    }
}

// ---------------- attention: m32/warp, 8 warps, 2 CTAs/SM ----------------
// QK^T and PV both bf16-3x; P in registers; B fragments reused across mb.
#define KP 20
#define VS 40
#define KPL (256 * KP)
#define VPL (128 * VS)
#define AT 256
#define ATTN_SMEM ((2 * KPL + 2 * VPL) * 4)   // 81920 B

__global__ void __launch_bounds__(AT, 2)
attn_mma() {
    extern __shared__ uint32_t smu[];
    uint32_t* Kh  = smu;
    uint32_t* Kl  = smu + KPL;
    uint32_t* Vph = smu + 2 * KPL;
    uint32_t* Vpl = Vph + VPL;

    int i = blockIdx.x, h = blockIdx.y;
    int tid = threadIdx.x;
    int w = tid >> 5, lane = tid & 31;
    int g = lane >> 2, t = lane & 3;
    int coff = h * D;
    size_t gbase = (size_t)i * N;
    const float sc2 = 0.17677669529663687f * LOG2E;

    // --- stage K: pairs along d (hi/lo, truncation split) ---
    #pragma unroll
    for (int it = 0; it < 8; it++) {
        int idx = tid + it * AT;
        int tok = idx >> 3, f = idx & 7;
        float4 kv = *(const float4*)(g_k + (gbase + tok) * C + coff + f * 4);
        float h0 = trunc_hi(kv.x), h1 = trunc_hi(kv.y);
        float h2 = trunc_hi(kv.z), h3 = trunc_hi(kv.w);
        uint32_t* kh = Kh + tok * KP + f * 2;
        uint32_t* kl = Kl + tok * KP + f * 2;
        kh[0] = hipack(kv.x, kv.y);
        kh[1] = hipack(kv.z, kv.w);
        kl[0] = bf16pair(kv.x - h0, kv.y - h1);
        kl[1] = bf16pair(kv.z - h2, kv.w - h3);
    }
    // --- stage V: pairs along tokens (hi/lo, truncation split) ---
    #pragma unroll
    for (int it = 0; it < 4; it++) {
        int idx = tid + it * AT;
        int m = idx >> 3, q = idx & 7;
        size_t b0 = (gbase + 2 * m) * C + coff + 4 * q;
        float4 f0 = *(const float4*)(g_v + b0);
        float4 f1 = *(const float4*)(g_v + b0 + C);
        uint4 hw, lw;
        float a0 = trunc_hi(f0.x), b0v = trunc_hi(f1.x);
        float a1 = trunc_hi(f0.y), b1v = trunc_hi(f1.y);
        float a2 = trunc_hi(f0.z), b2v = trunc_hi(f1.z);
        float a3 = trunc_hi(f0.w), b3v = trunc_hi(f1.w);
        hw.x = hipack(f0.x, f1.x);
        hw.y = hipack(f0.y, f1.y);
        hw.z = hipack(f0.z, f1.z);
        hw.w = hipack(f0.w, f1.w);
        lw.x = bf16pair(f0.x - a0, f1.x - b0v);
        lw.y = bf16pair(f0.y - a1, f1.y - b1v);
        lw.z = bf16pair(f0.z - a2, f1.z - b2v);
        lw.w = bf16pair(f0.w - a3, f1.w - b3v);
        *(uint4*)(Vph + m * VS + 4 * q) = hw;
        *(uint4*)(Vpl + m * VS + 4 * q) = lw;
    }

    // --- Q (scaled) registers, hi/lo pairs, 2 m-blocks per warp ---
    int jb = w * 32;
    uint32_t qh[2][2][4], ql[2][2][4];
    #pragma unroll
    for (int mb = 0; mb < 2; mb++) {
        int j1 = jb + mb * 16 + g, j2 = j1 + 8;
        #pragma unroll
        for (int ks = 0; ks < 2; ks++) {
            int d0 = 2 * (ks * 8 + t), d1 = 2 * (ks * 8 + t + 4);
            float2 qa = *(const float2*)(g_q + (gbase + j1) * C + coff + d0);
            float2 qb = *(const float2*)(g_q + (gbase + j2) * C + coff + d0);
            float2 qc = *(const float2*)(g_q + (gbase + j1) * C + coff + d1);
            float2 qd = *(const float2*)(g_q + (gbase + j2) * C + coff + d1);
            qa.x *= sc2; qa.y *= sc2; qb.x *= sc2; qb.y *= sc2;
            qc.x *= sc2; qc.y *= sc2; qd.x *= sc2; qd.y *= sc2;
            float a0 = trunc_hi(qa.x), a1 = trunc_hi(qa.y);
            float b0 = trunc_hi(qb.x), b1 = trunc_hi(qb.y);
            float c0 = trunc_hi(qc.x), c1 = trunc_hi(qc.y);
            float e0 = trunc_hi(qd.x), e1 = trunc_hi(qd.y);
            qh[mb][ks][0] = hipack(qa.x, qa.y);
            qh[mb][ks][1] = hipack(qb.x, qb.y);
            qh[mb][ks][2] = hipack(qc.x, qc.y);
            qh[mb][ks][3] = hipack(qd.x, qd.y);
            ql[mb][ks][0] = bf16pair(qa.x - a0, qa.y - a1);
            ql[mb][ks][1] = bf16pair(qb.x - b0, qb.y - b1);
            ql[mb][ks][2] = bf16pair(qc.x - c0, qc.y - c1);
            ql[mb][ks][3] = bf16pair(qd.x - e0, qd.y - e1);
        }
    }
    __syncthreads();

    float o[2][4][4];
    #pragma unroll
    for (int mb = 0; mb < 2; mb++)
        #pragma unroll
        for (int nb = 0; nb < 4; nb++)
            #pragma unroll
            for (int r = 0; r < 4; r++) o[mb][nb][r] = 0.0f;
    float lsum[2][2] = {{0.f, 0.f}, {0.f, 0.f}};

    const float* bbase = g_bt + (size_t)h * NT;

    for (int ch = 0; ch < 8; ch++) {
        int tok0 = ch * 32;
        // ---- S = Q K^T (bf16-3x), B fragment shared across mb ----
        float s[2][4][4];
        #pragma unroll
        for (int mb = 0; mb < 2; mb++)
            #pragma unroll
            for (int nt = 0; nt < 4; nt++)
                #pragma unroll
                for (int r = 0; r < 4; r++) s[mb][nt][r] = 0.0f;
        #pragma unroll
        for (int nt = 0; nt < 4; nt++) {
            int tokn = tok0 + nt * 8 + g;
            #pragma unroll
            for (int ks = 0; ks < 2; ks++) {
                uint32_t bh2[2], bl2[2];
                const uint32_t* kh = Kh + tokn * KP + ks * 8;
                const uint32_t* kl = Kl + tokn * KP + ks * 8;
                bh2[0] = kh[t]; bh2[1] = kh[t + 4];
                bl2[0] = kl[t]; bl2[1] = kl[t + 4];
                #pragma unroll
                for (int mb = 0; mb < 2; mb++) {
                    mma_bf16(s[mb][nt], qh[mb][ks], bh2);
                    mma_bf16(s[mb][nt], qh[mb][ks], bl2);
                    mma_bf16(s[mb][nt], ql[mb][ks], bh2);
                }
            }
        }
        // ---- bias + ex2 ----
        #pragma unroll
        for (int mb = 0; mb < 2; mb++) {
            int j1 = jb + mb * 16 + g;
            const float* bj1 = bbase + (size_t)j1 * N;
            const float* bj2 = bbase + (size_t)(j1 + 8) * N;
            #pragma unroll
            for (int nt = 0; nt < 4; nt++) {
                int k0 = tok0 + nt * 8 + 2 * t;
                float2 ba = *(const float2*)(bj1 + k0);
                float2 bb = *(const float2*)(bj2 + k0);
                s[mb][nt][0] = ex2f(s[mb][nt][0] + ba.x);
                s[mb][nt][1] = ex2f(s[mb][nt][1] + ba.y);
                s[mb][nt][2] = ex2f(s[mb][nt][2] + bb.x);
                s[mb][nt][3] = ex2f(s[mb][nt][3] + bb.y);
                lsum[mb][0] += s[mb][nt][0] + s[mb][nt][1];
                lsum[mb][1] += s[mb][nt][2] + s[mb][nt][3];
            }
        }
        // ---- PV per kt: pack both mb, then V fragment shared across mb ----
        int tp0 = tok0 >> 1;
        #pragma unroll
        for (int kt = 0; kt < 2; kt++) {
            uint32_t aPh[2][4], aPl[2][4];
            #pragma unroll
            for (int mb = 0; mb < 2; mb++) {
                const float* p0 = s[mb][2 * kt];
                const float* p1 = s[mb][2 * kt + 1];
                float r00 = p0[0] - trunc_hi(p0[0]), r01 = p0[1] - trunc_hi(p0[1]);
                float r02 = p0[2] - trunc_hi(p0[2]), r03 = p0[3] - trunc_hi(p0[3]);
                float r10 = p1[0] - trunc_hi(p1[0]), r11 = p1[1] - trunc_hi(p1[1]);
                float r12 = p1[2] - trunc_hi(p1[2]), r13 = p1[3] - trunc_hi(p1[3]);
                aPh[mb][0] = hipack(p0[0], p0[1]);
                aPh[mb][1] = hipack(p0[2], p0[3]);
                aPh[mb][2] = hipack(p1[0], p1[1]);
                aPh[mb][3] = hipack(p1[2], p1[3]);
                aPl[mb][0] = bf16pair(r00, r01);
                aPl[mb][1] = bf16pair(r02, r03);
                aPl[mb][2] = bf16pair(r10, r11);
                aPl[mb][3] = bf16pair(r12, r13);
            }
            #pragma unroll
            for (int nb = 0; nb < 4; nb++) {
                const uint32_t* vph = Vph + (tp0 + kt * 8 + t) * VS + nb * 8 + g;
                const uint32_t* vpl = Vpl + (tp0 + kt * 8 + t) * VS + nb * 8 + g;
                uint32_t vh[2], vl[2];
                vh[0] = vph[0]; vh[1] = vph[4 * VS];
                vl[0] = vpl[0]; vl[1] = vpl[4 * VS];
                #pragma unroll
                for (int mb = 0; mb < 2; mb++) {
                    mma_bf16(o[mb][nb], aPh[mb], vh);
                    mma_bf16(o[mb][nb], aPh[mb], vl);
                    mma_bf16(o[mb][nb], aPl[mb], vh);
                }
            }
        }
    }

    // ---- normalize, gate, store ----
    #pragma unroll
    for (int mb = 0; mb < 2; mb++) {
        float la = lsum[mb][0], lb = lsum[mb][1];
        la += __shfl_xor_sync(0xffffffffu, la, 1);
        la += __shfl_xor_sync(0xffffffffu, la, 2);
        lb += __shfl_xor_sync(0xffffffffu, lb, 1);
        lb += __shfl_xor_sync(0xffffffffu, lb, 2);
        float inv1 = 1.0f / la, inv2 = 1.0f / lb;
        int j1 = jb + mb * 16 + g, j2 = j1 + 8;
        #pragma unroll
        for (int nb = 0; nb < 4; nb++) {
            int d = nb * 8 + 2 * t;
            float2 g1 = *(const float2*)(g_g + (gbase + j1) * C + coff + d);
            float2 g2 = *(const float2*)(g_g + (gbase + j2) * C + coff + d);
            float2 o1, o2;
            o1.x = g1.x * o[mb][nb][0] * inv1;
            o1.y = g1.y * o[mb][nb][1] * inv1;
            o2.x = g2.x * o[mb][nb][2] * inv2;
            o2.y = g2.y * o[mb][nb][3] * inv2;
            *(float2*)(g_o + (gbase + j1) * C + coff + d) = o1;
            *(float2*)(g_o + (gbase + j2) * C + coff + d) = o2;
        }
    }
}

extern "C" void kernel_launch(void* const* d_in, const int* in_sizes, int n_in,
                              void* d_out, int out_size) {
    const float* z     = (const float*)d_in[0];
    const float* gamma = (const float*)d_in[1];
    const float* beta  = (const float*)d_in[2];
    const float* Wq    = (const float*)d_in[3];
    const float* Wk    = (const float*)d_in[4];
    const float* Wv    = (const float*)d_in[5];
    const float* Wb    = (const float*)d_in[6];
    const float* Wg    = (const float*)d_in[7];
    const float* Wout  = (const float*)d_in[8];
    float* out = (float*)d_out;

    void *p_lnz, *p_q, *p_k, *p_v, *p_g, *p_o;
    cudaGetSymbolAddress(&p_lnz, g_lnz);
    cudaGetSymbolAddress(&p_q, g_q);
    cudaGetSymbolAddress(&p_k, g_k);
    cudaGetSymbolAddress(&p_v, g_v);
    cudaGetSymbolAddress(&p_g, g_g);
    cudaGetSymbolAddress(&p_o, g_o);

    cudaFuncSetAttribute(gemm_fused,
                         cudaFuncAttributeMaxDynamicSharedMemorySize, GEMM_SMEM);
    cudaFuncSetAttribute(attn_mma,
                         cudaFuncAttributeMaxDynamicSharedMemorySize, ATTN_SMEM);

    ln_kernel<<<NT / 8, 256>>>(z, gamma, beta, Wb);
    W5 ws; ws.w[0] = Wq; ws.w[1] = Wk; ws.w[2] = Wv; ws.w[3] = Wg; ws.w[4] = Wout;
    wprep_kernel<<<dim3(32, 5), 256>>>(ws);

    Y4 yq; yq.p[0] = (float*)p_q; yq.p[1] = (float*)p_k;
    yq.p[2] = (float*)p_v; yq.p[3] = (float*)p_g;
    gemm_fused<<<NT / 128, GT, GEMM_SMEM>>>((const float*)p_lnz, 0, 4, yq, 0x8);

    attn_mma<<<dim3(N, H), AT, ATTN_SMEM>>>();

    Y4 yo; yo.p[0] = out; yo.p[1] = yo.p[2] = yo.p[3] = nullptr;
    gemm_fused<<<NT / 128, GT, GEMM_SMEM>>>((const float*)p_o, 4, 1, yo, 0);
}

// round 14
// speedup vs baseline: 1.5122x; 1.0388x over previous
#include <cuda_runtime.h>
#include <cuda_bf16.h>
#include <math.h>
#include <stdint.h>

#define N 256
#define NT (N*N)
#define C 128
#define H 4
#define D 32

// -------- scratch (device globals; no allocation allowed) --------
__device__ uint32_t g_xh[NT*64];   // LN output, bf16 hi pairs [tok][64]
__device__ uint32_t g_xl[NT*64];   // LN output, bf16 lo pairs
__device__ float    g_q[NT*C];
__device__ float    g_k[NT*C];
__device__ float    g_v[NT*C];
__device__ float    g_g[NT*C];     // sigmoid(z@Wg)
__device__ float    g_bt[H*NT];    // bias*log2e: [h][j][k]
__device__ uint32_t g_oh[NT*64];   // gated attn output, bf16 hi pairs
__device__ uint32_t g_ol[NT*64];   // gated attn output, bf16 lo pairs
__device__ uint32_t g_wph[5*C*(C/2)];
__device__ uint32_t g_wpl[5*C*(C/2)];

struct Y4 { float* p[4]; };
struct W5 { const float* w[5]; };

// ---------- helpers ----------
__device__ __forceinline__ uint32_t bf16pair(float even, float odd) {
    uint32_t r;
    asm("cvt.rn.satfinite.bf16x2.f32 %0, %1, %2;" : "=r"(r) : "f"(odd), "f"(even));
    return r;
}
__device__ __forceinline__ float trunc_hi(float x) {
    return __uint_as_float(__float_as_uint(x) & 0xFFFF0000u);
}
__device__ __forceinline__ uint32_t hipack(float a, float b) {
    return __byte_perm(__float_as_uint(a), __float_as_uint(b), 0x7632);
}
__device__ __forceinline__ float ex2f(float x) {
    float y;
    asm("ex2.approx.f32 %0, %1;" : "=f"(y) : "f"(x));
    return y;
}
__device__ __forceinline__ void mma_bf16(float* c, const uint32_t* a,
                                         const uint32_t* b) {
    asm volatile(
        "mma.sync.aligned.m16n8k16.row.col.f32.bf16.bf16.f32 "
        "{%0,%1,%2,%3},{%4,%5,%6,%7},{%8,%9},{%0,%1,%2,%3};"
        : "+f"(c[0]), "+f"(c[1]), "+f"(c[2]), "+f"(c[3])
        : "r"(a[0]), "r"(a[1]), "r"(a[2]), "r"(a[3]), "r"(b[0]), "r"(b[1]));
}
__device__ __forceinline__ void cp16(uint32_t* smem_dst, const void* gsrc) {
    uint32_t s = (uint32_t)__cvta_generic_to_shared(smem_dst);
    asm volatile("cp.async.cg.shared.global [%0], [%1], 16;\n"
                 :: "r"(s), "l"(gsrc));
}

#define LOG2E 1.4426950408889634f

// ---------------- LayerNorm + fused bias; writes packed hi/lo planes ----------------
__global__ void ln_kernel(const float* __restrict__ z,
                          const float* __restrict__ gamma,
                          const float* __restrict__ beta,
                          const float* __restrict__ Wb) {
    int warp = threadIdx.x >> 5, lane = threadIdx.x & 31;
    int t = blockIdx.x * 8 + warp;
    const float4 v = *(const float4*)(z + (size_t)t * C + lane * 4);
    float s = v.x + v.y + v.z + v.w;
    #pragma unroll
    for (int o = 16; o; o >>= 1) s += __shfl_xor_sync(0xffffffffu, s, o);
    float mu = s * (1.0f / C);
    float d0 = v.x - mu, d1 = v.y - mu, d2 = v.z - mu, d3 = v.w - mu;
    float vs = d0*d0 + d1*d1 + d2*d2 + d3*d3;
    #pragma unroll
    for (int o = 16; o; o >>= 1) vs += __shfl_xor_sync(0xffffffffu, vs, o);
    float r = rsqrtf(vs * (1.0f / C) + 1e-5f);
    float4 gm = *(const float4*)(gamma + lane * 4);
    float4 bt = *(const float4*)(beta + lane * 4);
    float4 out;
    out.x = d0 * r * gm.x + bt.x;
    out.y = d1 * r * gm.y + bt.y;
    out.z = d2 * r * gm.z + bt.z;
    out.w = d3 * r * gm.w + bt.w;

    // packed hi/lo planes for GEMM consumption
    uint2 hp, lp;
    hp.x = hipack(out.x, out.y);
    hp.y = hipack(out.z, out.w);
    lp.x = bf16pair(out.x - trunc_hi(out.x), out.y - trunc_hi(out.y));
    lp.y = bf16pair(out.z - trunc_hi(out.z), out.w - trunc_hi(out.w));
    size_t px = (size_t)t * 64 + lane * 2;
    *(uint2*)(g_xh + px) = hp;
    *(uint2*)(g_xl + px) = lp;

    float4 w0 = *(const float4*)(Wb + lane * 16);
    float4 w1 = *(const float4*)(Wb + lane * 16 + 4);
    float4 w2 = *(const float4*)(Wb + lane * 16 + 8);
    float4 w3 = *(const float4*)(Wb + lane * 16 + 12);
    float4 p;
    p.x = out.x * w0.x + out.y * w1.x + out.z * w2.x + out.w * w3.x;
    p.y = out.x * w0.y + out.y * w1.y + out.z * w2.y + out.w * w3.y;
    p.z = out.x * w0.z + out.y * w1.z + out.z * w2.z + out.w * w3.z;
    p.w = out.x * w0.w + out.y * w1.w + out.z * w2.w + out.w * w3.w;
    #pragma unroll
    for (int o = 16; o; o >>= 1) {
        p.x += __shfl_xor_sync(0xffffffffu, p.x, o);
        p.y += __shfl_xor_sync(0xffffffffu, p.y, o);
        p.z += __shfl_xor_sync(0xffffffffu, p.z, o);
        p.w += __shfl_xor_sync(0xffffffffu, p.w, o);
    }
    if (lane == 0) {
        int j = t >> 8, k = t & 255;
        size_t o2 = (size_t)j * N + k;
        g_bt[0 * NT + o2] = p.x * LOG2E;
        g_bt[1 * NT + o2] = p.y * LOG2E;
        g_bt[2 * NT + o2] = p.z * LOG2E;
        g_bt[3 * NT + o2] = p.w * LOG2E;
    }
}

// ------- weight prep: split + pack + transpose -------
__global__ void wprep_kernel(W5 ws) {
    int mat = blockIdx.y;
    int idx = blockIdx.x * 256 + threadIdx.x;
    int n = idx >> 6, k2 = idx & 63;
    const float* W = ws.w[mat];
    float w0 = W[(2 * k2) * C + n];
    float w1 = W[(2 * k2 + 1) * C + n];
    float h0 = trunc_hi(w0), h1 = trunc_hi(w1);
    g_wph[mat * 8192 + n * 64 + k2] = hipack(w0, w1);
    g_wpl[mat * 8192 + n * 64 + k2] = bf16pair(w0 - h0, w1 - h1);
}

// ---------------- bf16-3x GEMM: 64-row tiles, 256 thr, 2 CTAs/SM ----------------
// X given as packed hi/lo planes [tok][64]; staging is pure cp.async.
#define XW 68
#define XP2 (64 * XW)            // 4352 words per X plane
#define WP (128 * XW)            // 8704 words per W plane
#define GEMM_SMEM ((2 * XP2 + 2 * WP) * 4)   // 104448 B
#define GT 256

__global__ void __launch_bounds__(GT, 2)
gemm_ps(const uint32_t* __restrict__ Xh, const uint32_t* __restrict__ Xl,
        int slot0, int nmat, Y4 ys, int sigmask) {
    extern __shared__ uint32_t sm4[];
    uint32_t* Xh2 = sm4;             // [64][XW]
    uint32_t* Xl2 = sm4 + XP2;
    uint32_t* Wh2 = sm4 + 2 * XP2;   // [128][XW]
    uint32_t* Wl2 = Wh2 + WP;

    int tid = threadIdx.x;
    int warp = tid >> 5, lane = tid & 31;
    int g = lane >> 2, t = lane & 3;
    int wm = warp >> 2, wn = warp & 3;
    int row0 = blockIdx.x * 64;

    auto issueW = [&](int s) {
        #pragma unroll
        for (int i = 0; i < 16; i++) {
            int id = tid + i * GT;
            int plane = id >> 11, r = id & 2047;
            int n = r >> 4, q = r & 15;
            const uint32_t* src =
                (plane ? g_wpl : g_wph) + (slot0 + s) * 8192 + n * 64 + q * 4;
            cp16((plane ? Wl2 : Wh2) + n * XW + q * 4, src);
        }
    };

    // stage X (cp.async) + W0
    #pragma unroll
    for (int i = 0; i < 8; i++) {
        int id = tid + i * GT;
        int plane = id >> 10, r = id & 1023;
        int row = r >> 4, q = r & 15;
        const uint32_t* src = (plane ? Xl : Xh) + (size_t)(row0 + row) * 64 + q * 4;
        cp16((plane ? Xl2 : Xh2) + row * XW + q * 4, src);
    }
    issueW(0);
    asm volatile("cp.async.commit_group;\n");
    asm volatile("cp.async.wait_group 0;\n");
    __syncthreads();

    #pragma unroll 1
    for (int s = 0; s < nmat; s++) {
        float c[2][4][4];
        #pragma unroll
        for (int mb = 0; mb < 2; mb++)
            #pragma unroll
            for (int nb = 0; nb < 4; nb++)
                #pragma unroll
                for (int r = 0; r < 4; r++) c[mb][nb][r] = 0.0f;

        #pragma unroll
        for (int ks = 0; ks < 8; ks++) {
            int kb = ks * 8;
            uint32_t bh[4][2], bl[4][2];
            #pragma unroll
            for (int nb = 0; nb < 4; nb++) {
                int n = wn * 32 + nb * 8 + g;
                bh[nb][0] = Wh2[n * XW + kb + t];
                bh[nb][1] = Wh2[n * XW + kb + t + 4];
                bl[nb][0] = Wl2[n * XW + kb + t];
                bl[nb][1] = Wl2[n * XW + kb + t + 4];
            }
            #pragma unroll
            for (int mb = 0; mb < 2; mb++) {
                int r = wm * 32 + mb * 16 + g;
                uint32_t ah[4], al[4];
                ah[0] = Xh2[r * XW + kb + t];
                ah[1] = Xh2[(r + 8) * XW + kb + t];
                ah[2] = Xh2[r * XW + kb + t + 4];
                ah[3] = Xh2[(r + 8) * XW + kb + t + 4];
                al[0] = Xl2[r * XW + kb + t];
                al[1] = Xl2[(r + 8) * XW + kb + t];
                al[2] = Xl2[r * XW + kb + t + 4];
                al[3] = Xl2[(r + 8) * XW + kb + t + 4];
                #pragma unroll
                for (int nb = 0; nb < 4; nb++) {
                    mma_bf16(c[mb][nb], ah, bh[nb]);
                    mma_bf16(c[mb][nb], ah, bl[nb]);
                    mma_bf16(c[mb][nb], al, bh[nb]);
                }
            }
        }
        __syncthreads();    // everyone done reading W(s)

        if (s + 1 < nmat) {
            issueW(s + 1);  // overlap next-W load with epilogue stores
            asm volatile("cp.async.commit_group;\n");
        }

        float* Y = ys.p[s];
        int sg = (sigmask >> s) & 1;
        #pragma unroll
        for (int mb = 0; mb < 2; mb++) {
            int r0 = row0 + wm * 32 + mb * 16 + g;
            #pragma unroll
            for (int nb = 0; nb < 4; nb++) {
                int col = wn * 32 + nb * 8 + 2 * t;
                float v0 = c[mb][nb][0], v1 = c[mb][nb][1];
                float v2 = c[mb][nb][2], v3 = c[mb][nb][3];
                if (sg) {
                    v0 = 1.0f / (1.0f + __expf(-v0));
                    v1 = 1.0f / (1.0f + __expf(-v1));
                    v2 = 1.0f / (1.0f + __expf(-v2));
                    v3 = 1.0f / (1.0f + __expf(-v3));
                }
                *(float2*)(Y + (size_t)r0 * C + col) = make_float2(v0, v1);
                *(float2*)(Y + (size_t)(r0 + 8) * C + col) = make_float2(v2, v3);
            }
        }
        if (s + 1 < nmat) {
            asm volatile("cp.async.wait_group 0;\n");
            __syncthreads();
        }
    }
}

// ---------------- attention: m32/warp, 8 warps, 2 CTAs/SM ----------------
#define KP 20
#define VS 40
#define KPL (256 * KP)
#define VPL (128 * VS)
#define AT 256
#define ATTN_SMEM ((2 * KPL + 2 * VPL) * 4)   // 81920 B

__global__ void __launch_bounds__(AT, 2)
attn_mma() {
    extern __shared__ uint32_t smu[];
    uint32_t* Kh  = smu;
    uint32_t* Kl  = smu + KPL;
    uint32_t* Vph = smu + 2 * KPL;
    uint32_t* Vpl = Vph + VPL;

    int i = blockIdx.x, h = blockIdx.y;
    int tid = threadIdx.x;
    int w = tid >> 5, lane = tid & 31;
    int g = lane >> 2, t = lane & 3;
    int coff = h * D;
    size_t gbase = (size_t)i * N;
    const float sc2 = 0.17677669529663687f * LOG2E;

    #pragma unroll
    for (int it = 0; it < 8; it++) {
        int idx = tid + it * AT;
        int tok = idx >> 3, f = idx & 7;
        float4 kv = *(const float4*)(g_k + (gbase + tok) * C + coff + f * 4);
        float h0 = trunc_hi(kv.x), h1 = trunc_hi(kv.y);
        float h2 = trunc_hi(kv.z), h3 = trunc_hi(kv.w);
        uint32_t* kh = Kh + tok * KP + f * 2;
        uint32_t* kl = Kl + tok * KP + f * 2;
        kh[0] = hipack(kv.x, kv.y);
        kh[1] = hipack(kv.z, kv.w);
        kl[0] = bf16pair(kv.x - h0, kv.y - h1);
        kl[1] = bf16pair(kv.z - h2, kv.w - h3);
    }
    #pragma unroll
    for (int it = 0; it < 4; it++) {
        int idx = tid + it * AT;
        int m = idx >> 3, q = idx & 7;
        size_t b0 = (gbase + 2 * m) * C + coff + 4 * q;
        float4 f0 = *(const float4*)(g_v + b0);
        float4 f1 = *(const float4*)(g_v + b0 + C);
        uint4 hw, lw;
        float a0 = trunc_hi(f0.x), b0v = trunc_hi(f1.x);
        float a1 = trunc_hi(f0.y), b1v = trunc_hi(f1.y);
        float a2 = trunc_hi(f0.z), b2v = trunc_hi(f1.z);
        float a3 = trunc_hi(f0.w), b3v = trunc_hi(f1.w);
        hw.x = hipack(f0.x, f1.x);
        hw.y = hipack(f0.y, f1.y);
        hw.z = hipack(f0.z, f1.z);
        hw.w = hipack(f0.w, f1.w);
        lw.x = bf16pair(f0.x - a0, f1.x - b0v);
        lw.y = bf16pair(f0.y - a1, f1.y - b1v);
        lw.z = bf16pair(f0.z - a2, f1.z - b2v);
        lw.w = bf16pair(f0.w - a3, f1.w - b3v);
        *(uint4*)(Vph + m * VS + 4 * q) = hw;
        *(uint4*)(Vpl + m * VS + 4 * q) = lw;
    }

    int jb = w * 32;
    uint32_t qh[2][2][4], ql[2][2][4];
    #pragma unroll
    for (int mb = 0; mb < 2; mb++) {
        int j1 = jb + mb * 16 + g, j2 = j1 + 8;
        #pragma unroll
        for (int ks = 0; ks < 2; ks++) {
            int d0 = 2 * (ks * 8 + t), d1 = 2 * (ks * 8 + t + 4);
            float2 qa = *(const float2*)(g_q + (gbase + j1) * C + coff + d0);
            float2 qb = *(const float2*)(g_q + (gbase + j2) * C + coff + d0);
            float2 qc = *(const float2*)(g_q + (gbase + j1) * C + coff + d1);
            float2 qd = *(const float2*)(g_q + (gbase + j2) * C + coff + d1);
            qa.x *= sc2; qa.y *= sc2; qb.x *= sc2; qb.y *= sc2;
            qc.x *= sc2; qc.y *= sc2; qd.x *= sc2; qd.y *= sc2;
            float a0 = trunc_hi(qa.x), a1 = trunc_hi(qa.y);
            float b0 = trunc_hi(qb.x), b1 = trunc_hi(qb.y);
            float c0 = trunc_hi(qc.x), c1 = trunc_hi(qc.y);
            float e0 = trunc_hi(qd.x), e1 = trunc_hi(qd.y);
            qh[mb][ks][0] = hipack(qa.x, qa.y);
            qh[mb][ks][1] = hipack(qb.x, qb.y);
            qh[mb][ks][2] = hipack(qc.x, qc.y);
            qh[mb][ks][3] = hipack(qd.x, qd.y);
            ql[mb][ks][0] = bf16pair(qa.x - a0, qa.y - a1);
            ql[mb][ks][1] = bf16pair(qb.x - b0, qb.y - b1);
            ql[mb][ks][2] = bf16pair(qc.x - c0, qc.y - c1);
            ql[mb][ks][3] = bf16pair(qd.x - e0, qd.y - e1);
        }
    }
    __syncthreads();

    float o[2][4][4];
    #pragma unroll
    for (int mb = 0; mb < 2; mb++)
        #pragma unroll
        for (int nb = 0; nb < 4; nb++)
            #pragma unroll
            for (int r = 0; r < 4; r++) o[mb][nb][r] = 0.0f;
    float lsum[2][2] = {{0.f, 0.f}, {0.f, 0.f}};

    const float* bbase = g_bt + (size_t)h * NT;

    for (int ch = 0; ch < 8; ch++) {
        int tok0 = ch * 32;
        float s[2][4][4];
        #pragma unroll
        for (int mb = 0; mb < 2; mb++)
            #pragma unroll
            for (int nt = 0; nt < 4; nt++)
                #pragma unroll
                for (int r = 0; r < 4; r++) s[mb][nt][r] = 0.0f;
        #pragma unroll
        for (int nt = 0; nt < 4; nt++) {
            int tokn = tok0 + nt * 8 + g;
            #pragma unroll
            for (int ks = 0; ks < 2; ks++) {
                uint32_t bh2[2], bl2[2];
                const uint32_t* kh = Kh + tokn * KP + ks * 8;
                const uint32_t* kl = Kl + tokn * KP + ks * 8;
                bh2[0] = kh[t]; bh2[1] = kh[t + 4];
                bl2[0] = kl[t]; bl2[1] = kl[t + 4];
                #pragma unroll
                for (int mb = 0; mb < 2; mb++) {
                    mma_bf16(s[mb][nt], qh[mb][ks], bh2);
                    mma_bf16(s[mb][nt], qh[mb][ks], bl2);
                    mma_bf16(s[mb][nt], ql[mb][ks], bh2);
                }
            }
        }
        #pragma unroll
        for (int mb = 0; mb < 2; mb++) {
            int j1 = jb + mb * 16 + g;
            const float* bj1 = bbase + (size_t)j1 * N;
            const float* bj2 = bbase + (size_t)(j1 + 8) * N;
            #pragma unroll
            for (int nt = 0; nt < 4; nt++) {
                int k0 = tok0 + nt * 8 + 2 * t;
                float2 ba = *(const float2*)(bj1 + k0);
                float2 bb = *(const float2*)(bj2 + k0);
                s[mb][nt][0] = ex2f(s[mb][nt][0] + ba.x);
                s[mb][nt][1] = ex2f(s[mb][nt][1] + ba.y);
                s[mb][nt][2] = ex2f(s[mb][nt][2] + bb.x);
                s[mb][nt][3] = ex2f(s[mb][nt][3] + bb.y);
                lsum[mb][0] += s[mb][nt][0] + s[mb][nt][1];
                lsum[mb][1] += s[mb][nt][2] + s[mb][nt][3];
            }
        }
        int tp0 = tok0 >> 1;
        #pragma unroll
        for (int kt = 0; kt < 2; kt++) {
            uint32_t aPh[2][4], aPl[2][4];
            #pragma unroll
            for (int mb = 0; mb < 2; mb++) {
                const float* p0 = s[mb][2 * kt];
                const float* p1 = s[mb][2 * kt + 1];
                float r00 = p0[0] - trunc_hi(p0[0]), r01 = p0[1] - trunc_hi(p0[1]);
                float r02 = p0[2] - trunc_hi(p0[2]), r03 = p0[3] - trunc_hi(p0[3]);
                float r10 = p1[0] - trunc_hi(p1[0]), r11 = p1[1] - trunc_hi(p1[1]);
                float r12 = p1[2] - trunc_hi(p1[2]), r13 = p1[3] - trunc_hi(p1[3]);
                aPh[mb][0] = hipack(p0[0], p0[1]);
                aPh[mb][1] = hipack(p0[2], p0[3]);
                aPh[mb][2] = hipack(p1[0], p1[1]);
                aPh[mb][3] = hipack(p1[2], p1[3]);
                aPl[mb][0] = bf16pair(r00, r01);
                aPl[mb][1] = bf16pair(r02, r03);
                aPl[mb][2] = bf16pair(r10, r11);
                aPl[mb][3] = bf16pair(r12, r13);
            }
            #pragma unroll
            for (int nb = 0; nb < 4; nb++) {
                const uint32_t* vph = Vph + (tp0 + kt * 8 + t) * VS + nb * 8 + g;
                const uint32_t* vpl = Vpl + (tp0 + kt * 8 + t) * VS + nb * 8 + g;
                uint32_t vh[2], vl[2];
                vh[0] = vph[0]; vh[1] = vph[4 * VS];
                vl[0] = vpl[0]; vl[1] = vpl[4 * VS];
                #pragma unroll
                for (int mb = 0; mb < 2; mb++) {
                    mma_bf16(o[mb][nb], aPh[mb], vh);
                    mma_bf16(o[mb][nb], aPh[mb], vl);
                    mma_bf16(o[mb][nb], aPl[mb], vh);
                }
            }
        }
    }

    // ---- normalize, gate, store as packed hi/lo pair planes ----
    #pragma unroll
    for (int mb = 0; mb < 2; mb++) {
        float la = lsum[mb][0], lb = lsum[mb][1];
        la += __shfl_xor_sync(0xffffffffu, la, 1);
        la += __shfl_xor_sync(0xffffffffu, la, 2);
        lb += __shfl_xor_sync(0xffffffffu, lb, 1);
        lb += __shfl_xor_sync(0xffffffffu, lb, 2);
        float inv1 = 1.0f / la, inv2 = 1.0f / lb;
        int j1 = jb + mb * 16 + g, j2 = j1 + 8;
        #pragma unroll
        for (int nb = 0; nb < 4; nb++) {
            int d = nb * 8 + 2 * t;
            int pr = (coff >> 1) + nb * 4 + t;
            float2 g1 = *(const float2*)(g_g + (gbase + j1) * C + coff + d);
            float2 g2 = *(const float2*)(g_g + (gbase + j2) * C + coff + d);
            float o1x = g1.x * o[mb][nb][0] * inv1;
            float o1y = g1.y * o[mb][nb][1] * inv1;
            float o2x = g2.x * o[mb][nb][2] * inv2;
            float o2y = g2.y * o[mb][nb][3] * inv2;
            size_t p1 = (gbase + j1) * 64 + pr;
            size_t p2 = (gbase + j2) * 64 + pr;
            g_oh[p1] = hipack(o1x, o1y);
            g_ol[p1] = bf16pair(o1x - trunc_hi(o1x), o1y - trunc_hi(o1y));
            g_oh[p2] = hipack(o2x, o2y);
            g_ol[p2] = bf16pair(o2x - trunc_hi(o2x), o2y - trunc_hi(o2y));
        }
    }
}

extern "C" void kernel_launch(void* const* d_in, const int* in_sizes, int n_in,
                              void* d_out, int out_size) {
    const float* z     = (const float*)d_in[0];
    const float* gamma = (const float*)d_in[1];
    const float* beta  = (const float*)d_in[2];
    const float* Wq    = (const float*)d_in[3];
    const float* Wk    = (const float*)d_in[4];
    const float* Wv    = (const float*)d_in[5];
    const float* Wb    = (const float*)d_in[6];
    const float* Wg    = (const float*)d_in[7];
    const float* Wout  = (const float*)d_in[8];
    float* out = (float*)d_out;

    void *p_xh, *p_xl, *p_q, *p_k, *p_v, *p_g, *p_oh, *p_ol;
    cudaGetSymbolAddress(&p_xh, g_xh);
    cudaGetSymbolAddress(&p_xl, g_xl);
    cudaGetSymbolAddress(&p_q, g_q);
    cudaGetSymbolAddress(&p_k, g_k);
    cudaGetSymbolAddress(&p_v, g_v);
    cudaGetSymbolAddress(&p_g, g_g);
    cudaGetSymbolAddress(&p_oh, g_oh);
    cudaGetSymbolAddress(&p_ol, g_ol);

    cudaFuncSetAttribute(gemm_ps,
                         cudaFuncAttributeMaxDynamicSharedMemorySize, GEMM_SMEM);
    cudaFuncSetAttribute(attn_mma,
                         cudaFuncAttributeMaxDynamicSharedMemorySize, ATTN_SMEM);

    ln_kernel<<<NT / 8, 256>>>(z, gamma, beta, Wb);
    W5 ws; ws.w[0] = Wq; ws.w[1] = Wk; ws.w[2] = Wv; ws.w[3] = Wg; ws.w[4] = Wout;
    wprep_kernel<<<dim3(32, 5), 256>>>(ws);

    Y4 yq; yq.p[0] = (float*)p_q; yq.p[1] = (float*)p_k;
    yq.p[2] = (float*)p_v; yq.p[3] = (float*)p_g;
    gemm_ps<<<NT / 64, GT, GEMM_SMEM>>>((const uint32_t*)p_xh, (const uint32_t*)p_xl,
                                        0, 4, yq, 0x8);

    attn_mma<<<dim3(N, H), AT, ATTN_SMEM>>>();

    Y4 yo; yo.p[0] = out; yo.p[1] = yo.p[2] = yo.p[3] = nullptr;
    gemm_ps<<<NT / 64, GT, GEMM_SMEM>>>((const uint32_t*)p_oh, (const uint32_t*)p_ol,
                                        4, 1, yo, 0);
}

// round 16
// speedup vs baseline: 1.5420x; 1.0197x over previous
#include <cuda_runtime.h>
#include <cuda_bf16.h>
#include <math.h>
#include <stdint.h>

#define N 256
#define NT (N*N)
#define C 128
#define H 4
#define D 32

// -------- scratch (device globals; no allocation allowed) --------
__device__ uint32_t g_xh[NT*64];   // LN output, bf16 hi pairs [tok][64]
__device__ uint32_t g_xl[NT*64];   // LN output, bf16 lo pairs
__device__ float    g_q[NT*C];     // pre-scaled by sc*log2e (folded into Wq)
__device__ float    g_k[NT*C];
__device__ float    g_v[NT*C];
__device__ float    g_g[NT*C];     // sigmoid(z@Wg)
__device__ float    g_bt[H*NT];    // bias*log2e: [h][j][k]
__device__ uint32_t g_oh[NT*64];   // gated attn output, bf16 hi pairs
__device__ uint32_t g_ol[NT*64];   // gated attn output, bf16 lo pairs
__device__ uint32_t g_wph[5*C*(C/2)];
__device__ uint32_t g_wpl[5*C*(C/2)];

struct Y4 { float* p[4]; };
struct W5 { const float* w[5]; };

// ---------- helpers ----------
__device__ __forceinline__ uint32_t bf16pair(float even, float odd) {
    uint32_t r;
    asm("cvt.rn.satfinite.bf16x2.f32 %0, %1, %2;" : "=r"(r) : "f"(odd), "f"(even));
    return r;
}
__device__ __forceinline__ float trunc_hi(float x) {
    return __uint_as_float(__float_as_uint(x) & 0xFFFF0000u);
}
__device__ __forceinline__ uint32_t hipack(float a, float b) {
    return __byte_perm(__float_as_uint(a), __float_as_uint(b), 0x7632);
}
__device__ __forceinline__ float ex2f(float x) {
    float y;
    asm("ex2.approx.f32 %0, %1;" : "=f"(y) : "f"(x));
    return y;
}
__device__ __forceinline__ void mma_bf16(float* c, const uint32_t* a,
                                         const uint32_t* b) {
    asm volatile(
        "mma.sync.aligned.m16n8k16.row.col.f32.bf16.bf16.f32 "
        "{%0,%1,%2,%3},{%4,%5,%6,%7},{%8,%9},{%0,%1,%2,%3};"
        : "+f"(c[0]), "+f"(c[1]), "+f"(c[2]), "+f"(c[3])
        : "r"(a[0]), "r"(a[1]), "r"(a[2]), "r"(a[3]), "r"(b[0]), "r"(b[1]));
}
__device__ __forceinline__ void ldsm4(uint32_t& r0, uint32_t& r1,
                                      uint32_t& r2, uint32_t& r3, uint32_t sa) {
    asm volatile("ldmatrix.sync.aligned.m8n8.x4.shared.b16 {%0,%1,%2,%3}, [%4];"
                 : "=r"(r0), "=r"(r1), "=r"(r2), "=r"(r3) : "r"(sa));
}
__device__ __forceinline__ void cp16(uint32_t* smem_dst, const void* gsrc) {
    uint32_t s = (uint32_t)__cvta_generic_to_shared(smem_dst);
    asm volatile("cp.async.cg.shared.global [%0], [%1], 16;\n"
                 :: "r"(s), "l"(gsrc));
}

#define LOG2E 1.4426950408889634f
#define QSCALE (0.17677669529663687f * LOG2E)

// ---------------- LayerNorm + fused bias; writes packed hi/lo planes ----------------
__global__ void ln_kernel(const float* __restrict__ z,
                          const float* __restrict__ gamma,
                          const float* __restrict__ beta,
                          const float* __restrict__ Wb) {
    int warp = threadIdx.x >> 5, lane = threadIdx.x & 31;
    int t = blockIdx.x * 8 + warp;
    const float4 v = *(const float4*)(z + (size_t)t * C + lane * 4);
    float s = v.x + v.y + v.z + v.w;
    #pragma unroll
    for (int o = 16; o; o >>= 1) s += __shfl_xor_sync(0xffffffffu, s, o);
    float mu = s * (1.0f / C);
    float d0 = v.x - mu, d1 = v.y - mu, d2 = v.z - mu, d3 = v.w - mu;
    float vs = d0*d0 + d1*d1 + d2*d2 + d3*d3;
    #pragma unroll
    for (int o = 16; o; o >>= 1) vs += __shfl_xor_sync(0xffffffffu, vs, o);
    float r = rsqrtf(vs * (1.0f / C) + 1e-5f);
    float4 gm = *(const float4*)(gamma + lane * 4);
    float4 bt = *(const float4*)(beta + lane * 4);
    float4 out;
    out.x = d0 * r * gm.x + bt.x;
    out.y = d1 * r * gm.y + bt.y;
    out.z = d2 * r * gm.z + bt.z;
    out.w = d3 * r * gm.w + bt.w;

    uint2 hp, lp;
    hp.x = hipack(out.x, out.y);
    hp.y = hipack(out.z, out.w);
    lp.x = bf16pair(out.x - trunc_hi(out.x), out.y - trunc_hi(out.y));
    lp.y = bf16pair(out.z - trunc_hi(out.z), out.w - trunc_hi(out.w));
    size_t px = (size_t)t * 64 + lane * 2;
    *(uint2*)(g_xh + px) = hp;
    *(uint2*)(g_xl + px) = lp;

    float4 w0 = *(const float4*)(Wb + lane * 16);
    float4 w1 = *(const float4*)(Wb + lane * 16 + 4);
    float4 w2 = *(const float4*)(Wb + lane * 16 + 8);
    float4 w3 = *(const float4*)(Wb + lane * 16 + 12);
    float4 p;
    p.x = out.x * w0.x + out.y * w1.x + out.z * w2.x + out.w * w3.x;
    p.y = out.x * w0.y + out.y * w1.y + out.z * w2.y + out.w * w3.y;
    p.z = out.x * w0.z + out.y * w1.z + out.z * w2.z + out.w * w3.z;
    p.w = out.x * w0.w + out.y * w1.w + out.z * w2.w + out.w * w3.w;
    #pragma unroll
    for (int o = 16; o; o >>= 1) {
        p.x += __shfl_xor_sync(0xffffffffu, p.x, o);
        p.y += __shfl_xor_sync(0xffffffffu, p.y, o);
        p.z += __shfl_xor_sync(0xffffffffu, p.z, o);
        p.w += __shfl_xor_sync(0xffffffffu, p.w, o);
    }
    if (lane == 0) {
        int j = t >> 8, k = t & 255;
        size_t o2 = (size_t)j * N + k;
        g_bt[0 * NT + o2] = p.x * LOG2E;
        g_bt[1 * NT + o2] = p.y * LOG2E;
        g_bt[2 * NT + o2] = p.z * LOG2E;
        g_bt[3 * NT + o2] = p.w * LOG2E;
    }
}

// ------- weight prep: split + pack + transpose; Wq pre-scaled by QSCALE -------
__global__ void wprep_kernel(W5 ws) {
    int mat = blockIdx.y;
    int idx = blockIdx.x * 256 + threadIdx.x;
    int n = idx >> 6, k2 = idx & 63;
    const float* W = ws.w[mat];
    float sc = (mat == 0) ? QSCALE : 1.0f;
    float w0 = W[(2 * k2) * C + n] * sc;
    float w1 = W[(2 * k2 + 1) * C + n] * sc;
    float h0 = trunc_hi(w0), h1 = trunc_hi(w1);
    g_wph[mat * 8192 + n * 64 + k2] = hipack(w0, w1);
    g_wpl[mat * 8192 + n * 64 + k2] = bf16pair(w0 - h0, w1 - h1);
}

// ---------------- bf16-3x GEMM: 64-row tiles, 256 thr, 2 CTAs/SM, LDSM ----------------
#define XW 68
#define XP2 (64 * XW)
#define WP (128 * XW)
#define GEMM_SMEM ((2 * XP2 + 2 * WP) * 4)
#define GT 256

__global__ void __launch_bounds__(GT, 2)
gemm_ps(const uint32_t* __restrict__ Xh, const uint32_t* __restrict__ Xl,
        int slot0, int nmat, Y4 ys, int sigmask) {
    extern __shared__ uint32_t sm4[];
    uint32_t* Xh2 = sm4;
    uint32_t* Xl2 = sm4 + XP2;
    uint32_t* Wh2 = sm4 + 2 * XP2;
    uint32_t* Wl2 = Wh2 + WP;

    int tid = threadIdx.x;
    int warp = tid >> 5, lane = tid & 31;
    int g = lane >> 2, t = lane & 3;
    int wm = warp >> 2, wn = warp & 3;
    int row0 = blockIdx.x * 64;

    // LDSM lane address components
    int arow = (lane & 7) + ((lane >> 3) & 1) * 8;   // A: T0/T2 rows 0-7, T1/T3 rows 8-15
    int awoff = ((lane >> 4) & 1) * 4;               // A: T2/T3 at word +4
    int brow = (lane & 7) + ((lane >> 4) & 1) * 8;   // B: T2/T3 rows +8
    int bwoff = ((lane >> 3) & 1) * 4;               // B: T1/T3 at word +4
    uint32_t sXh = (uint32_t)__cvta_generic_to_shared(Xh2);
    uint32_t sXl = (uint32_t)__cvta_generic_to_shared(Xl2);
    uint32_t sWh = (uint32_t)__cvta_generic_to_shared(Wh2);
    uint32_t sWl = (uint32_t)__cvta_generic_to_shared(Wl2);

    auto issueW = [&](int s) {
        #pragma unroll
        for (int i = 0; i < 16; i++) {
            int id = tid + i * GT;
            int plane = id >> 11, r = id & 2047;
            int n = r >> 4, q = r & 15;
            const uint32_t* src =
                (plane ? g_wpl : g_wph) + (slot0 + s) * 8192 + n * 64 + q * 4;
            cp16((plane ? Wl2 : Wh2) + n * XW + q * 4, src);
        }
    };

    #pragma unroll
    for (int i = 0; i < 8; i++) {
        int id = tid + i * GT;
        int plane = id >> 10, r = id & 1023;
        int row = r >> 4, q = r & 15;
        const uint32_t* src = (plane ? Xl : Xh) + (size_t)(row0 + row) * 64 + q * 4;
        cp16((plane ? Xl2 : Xh2) + row * XW + q * 4, src);
    }
    issueW(0);
    asm volatile("cp.async.commit_group;\n");
    asm volatile("cp.async.wait_group 0;\n");
    __syncthreads();

    #pragma unroll 1
    for (int s = 0; s < nmat; s++) {
        float c[2][4][4];
        #pragma unroll
        for (int mb = 0; mb < 2; mb++)
            #pragma unroll
            for (int nb = 0; nb < 4; nb++)
                #pragma unroll
                for (int r = 0; r < 4; r++) c[mb][nb][r] = 0.0f;

        #pragma unroll
        for (int ks = 0; ks < 8; ks++) {
            int kb = ks * 8;
            uint32_t bh[4][2], bl[4][2];
            #pragma unroll
            for (int nbp = 0; nbp < 2; nbp++) {
                uint32_t off = 4u * ((wn * 32 + nbp * 16 + brow) * XW + kb + bwoff);
                ldsm4(bh[2*nbp][0], bh[2*nbp][1], bh[2*nbp+1][0], bh[2*nbp+1][1],
                      sWh + off);
                ldsm4(bl[2*nbp][0], bl[2*nbp][1], bl[2*nbp+1][0], bl[2*nbp+1][1],
                      sWl + off);
            }
            #pragma unroll
            for (int mb = 0; mb < 2; mb++) {
                uint32_t ah[4], al[4];
                uint32_t offa = 4u * ((wm * 32 + mb * 16 + arow) * XW + kb + awoff);
                ldsm4(ah[0], ah[1], ah[2], ah[3], sXh + offa);
                ldsm4(al[0], al[1], al[2], al[3], sXl + offa);
                #pragma unroll
                for (int nb = 0; nb < 4; nb++) {
                    mma_bf16(c[mb][nb], ah, bh[nb]);
                    mma_bf16(c[mb][nb], ah, bl[nb]);
                    mma_bf16(c[mb][nb], al, bh[nb]);
                }
            }
        }
        __syncthreads();

        if (s + 1 < nmat) {
            issueW(s + 1);
            asm volatile("cp.async.commit_group;\n");
        }

        float* Y = ys.p[s];
        int sg = (sigmask >> s) & 1;
        #pragma unroll
        for (int mb = 0; mb < 2; mb++) {
            int r0 = row0 + wm * 32 + mb * 16 + g;
            #pragma unroll
            for (int nb = 0; nb < 4; nb++) {
                int col = wn * 32 + nb * 8 + 2 * t;
                float v0 = c[mb][nb][0], v1 = c[mb][nb][1];
                float v2 = c[mb][nb][2], v3 = c[mb][nb][3];
                if (sg) {
                    v0 = 1.0f / (1.0f + __expf(-v0));
                    v1 = 1.0f / (1.0f + __expf(-v1));
                    v2 = 1.0f / (1.0f + __expf(-v2));
                    v3 = 1.0f / (1.0f + __expf(-v3));
                }
                *(float2*)(Y + (size_t)r0 * C + col) = make_float2(v0, v1);
                *(float2*)(Y + (size_t)(r0 + 8) * C + col) = make_float2(v2, v3);
            }
        }
        if (s + 1 < nmat) {
            asm volatile("cp.async.wait_group 0;\n");
            __syncthreads();
        }
    }
}

// ---------------- attention: m32/warp, 8 warps, 2 CTAs/SM, LDSM for K ----------------
// QK^T: bf16-3x. PV: bf16-3x (R14 numerics, Pl restored).
#define KP 20
#define VS 40
#define KPL (256 * KP)
#define VPL (128 * VS)
#define AT 256
#define ATTN_SMEM ((2 * KPL + 2 * VPL) * 4)

__global__ void __launch_bounds__(AT, 2)
attn_mma() {
    extern __shared__ uint32_t smu[];
    uint32_t* Kh  = smu;
    uint32_t* Kl  = smu + KPL;
    uint32_t* Vph = smu + 2 * KPL;
    uint32_t* Vpl = Vph + VPL;

    int i = blockIdx.x, h = blockIdx.y;
    int tid = threadIdx.x;
    int w = tid >> 5, lane = tid & 31;
    int g = lane >> 2, t = lane & 3;
    int coff = h * D;
    size_t gbase = (size_t)i * N;

    #pragma unroll
    for (int it = 0; it < 8; it++) {
        int idx = tid + it * AT;
        int tok = idx >> 3, f = idx & 7;
        float4 kv = *(const float4*)(g_k + (gbase + tok) * C + coff + f * 4);
        float h0 = trunc_hi(kv.x), h1 = trunc_hi(kv.y);
        float h2 = trunc_hi(kv.z), h3 = trunc_hi(kv.w);
        uint32_t* kh = Kh + tok * KP + f * 2;
        uint32_t* kl = Kl + tok * KP + f * 2;
        kh[0] = hipack(kv.x, kv.y);
        kh[1] = hipack(kv.z, kv.w);
        kl[0] = bf16pair(kv.x - h0, kv.y - h1);
        kl[1] = bf16pair(kv.z - h2, kv.w - h3);
    }
    #pragma unroll
    for (int it = 0; it < 4; it++) {
        int idx = tid + it * AT;
        int m = idx >> 3, q = idx & 7;
        size_t b0 = (gbase + 2 * m) * C + coff + 4 * q;
        float4 f0 = *(const float4*)(g_v + b0);
        float4 f1 = *(const float4*)(g_v + b0 + C);
        uint4 hw, lw;
        float a0 = trunc_hi(f0.x), b0v = trunc_hi(f1.x);
        float a1 = trunc_hi(f0.y), b1v = trunc_hi(f1.y);
        float a2 = trunc_hi(f0.z), b2v = trunc_hi(f1.z);
        float a3 = trunc_hi(f0.w), b3v = trunc_hi(f1.w);
        hw.x = hipack(f0.x, f1.x);
        hw.y = hipack(f0.y, f1.y);
        hw.z = hipack(f0.z, f1.z);
        hw.w = hipack(f0.w, f1.w);
        lw.x = bf16pair(f0.x - a0, f1.x - b0v);
        lw.y = bf16pair(f0.y - a1, f1.y - b1v);
        lw.z = bf16pair(f0.z - a2, f1.z - b2v);
        lw.w = bf16pair(f0.w - a3, f1.w - b3v);
        *(uint4*)(Vph + m * VS + 4 * q) = hw;
        *(uint4*)(Vpl + m * VS + 4 * q) = lw;
    }

    // Q pre-scaled (QSCALE folded into Wq)
    int jb = w * 32;
    uint32_t qh[2][2][4], ql[2][2][4];
    #pragma unroll
    for (int mb = 0; mb < 2; mb++) {
        int j1 = jb + mb * 16 + g, j2 = j1 + 8;
        #pragma unroll
        for (int ks = 0; ks < 2; ks++) {
            int d0 = 2 * (ks * 8 + t), d1 = 2 * (ks * 8 + t + 4);
            float2 qa = *(const float2*)(g_q + (gbase + j1) * C + coff + d0);
            float2 qb = *(const float2*)(g_q + (gbase + j2) * C + coff + d0);
            float2 qc = *(const float2*)(g_q + (gbase + j1) * C + coff + d1);
            float2 qd = *(const float2*)(g_q + (gbase + j2) * C + coff + d1);
            float a0 = trunc_hi(qa.x), a1 = trunc_hi(qa.y);
            float b0 = trunc_hi(qb.x), b1 = trunc_hi(qb.y);
            float c0 = trunc_hi(qc.x), c1 = trunc_hi(qc.y);
            float e0 = trunc_hi(qd.x), e1 = trunc_hi(qd.y);
            qh[mb][ks][0] = hipack(qa.x, qa.y);
            qh[mb][ks][1] = hipack(qb.x, qb.y);
            qh[mb][ks][2] = hipack(qc.x, qc.y);
            qh[mb][ks][3] = hipack(qd.x, qd.y);
            ql[mb][ks][0] = bf16pair(qa.x - a0, qa.y - a1);
            ql[mb][ks][1] = bf16pair(qb.x - b0, qb.y - b1);
            ql[mb][ks][2] = bf16pair(qc.x - c0, qc.y - c1);
            ql[mb][ks][3] = bf16pair(qd.x - e0, qd.y - e1);
        }
    }
    __syncthreads();

    float o[2][4][4];
    #pragma unroll
    for (int mb = 0; mb < 2; mb++)
        #pragma unroll
        for (int nb = 0; nb < 4; nb++)
            #pragma unroll
            for (int r = 0; r < 4; r++) o[mb][nb][r] = 0.0f;
    float lsum[2][2] = {{0.f, 0.f}, {0.f, 0.f}};

    const float* bbase = g_bt + (size_t)h * NT;
    // LDSM lane address components for K (x4: word tiles 0/4/8/12)
    int krow = lane & 7;
    int kwoff = (lane >> 3) * 4;
    uint32_t sKh = (uint32_t)__cvta_generic_to_shared(Kh);
    uint32_t sKl = (uint32_t)__cvta_generic_to_shared(Kl);

    for (int ch = 0; ch < 8; ch++) {
        int tok0 = ch * 32;
        float s[2][4][4];
        #pragma unroll
        for (int mb = 0; mb < 2; mb++)
            #pragma unroll
            for (int nt = 0; nt < 4; nt++)
                #pragma unroll
                for (int r = 0; r < 4; r++) s[mb][nt][r] = 0.0f;
        #pragma unroll
        for (int nt = 0; nt < 4; nt++) {
            uint32_t off = 4u * ((tok0 + nt * 8 + krow) * KP + kwoff);
            uint32_t kh0, kh1, kh2, kh3, kl0, kl1, kl2, kl3;
            ldsm4(kh0, kh1, kh2, kh3, sKh + off);
            ldsm4(kl0, kl1, kl2, kl3, sKl + off);
            uint32_t bh0[2] = {kh0, kh1}, bh1[2] = {kh2, kh3};
            uint32_t bl0[2] = {kl0, kl1}, bl1[2] = {kl2, kl3};
            #pragma unroll
            for (int mb = 0; mb < 2; mb++) {
                mma_bf16(s[mb][nt], qh[mb][0], bh0);
                mma_bf16(s[mb][nt], qh[mb][0], bl0);
                mma_bf16(s[mb][nt], ql[mb][0], bh0);
                mma_bf16(s[mb][nt], qh[mb][1], bh1);
                mma_bf16(s[mb][nt], qh[mb][1], bl1);
                mma_bf16(s[mb][nt], ql[mb][1], bh1);
            }
        }
        #pragma unroll
        for (int mb = 0; mb < 2; mb++) {
            int j1 = jb + mb * 16 + g;
            const float* bj1 = bbase + (size_t)j1 * N;
            const float* bj2 = bbase + (size_t)(j1 + 8) * N;
            #pragma unroll
            for (int nt = 0; nt < 4; nt++) {
                int k0 = tok0 + nt * 8 + 2 * t;
                float2 ba = *(const float2*)(bj1 + k0);
                float2 bb = *(const float2*)(bj2 + k0);
                s[mb][nt][0] = ex2f(s[mb][nt][0] + ba.x);
                s[mb][nt][1] = ex2f(s[mb][nt][1] + ba.y);
                s[mb][nt][2] = ex2f(s[mb][nt][2] + bb.x);
                s[mb][nt][3] = ex2f(s[mb][nt][3] + bb.y);
                lsum[mb][0] += s[mb][nt][0] + s[mb][nt][1];
                lsum[mb][1] += s[mb][nt][2] + s[mb][nt][3];
            }
        }
        int tp0 = tok0 >> 1;
        #pragma unroll
        for (int kt = 0; kt < 2; kt++) {
            uint32_t aPh[2][4], aPl[2][4];
            #pragma unroll
            for (int mb = 0; mb < 2; mb++) {
                const float* p0 = s[mb][2 * kt];
                const float* p1 = s[mb][2 * kt + 1];
                float r00 = p0[0] - trunc_hi(p0[0]), r01 = p0[1] - trunc_hi(p0[1]);
                float r02 = p0[2] - trunc_hi(p0[2]), r03 = p0[3] - trunc_hi(p0[3]);
                float r10 = p1[0] - trunc_hi(p1[0]), r11 = p1[1] - trunc_hi(p1[1]);
                float r12 = p1[2] - trunc_hi(p1[2]), r13 = p1[3] - trunc_hi(p1[3]);
                aPh[mb][0] = hipack(p0[0], p0[1]);
                aPh[mb][1] = hipack(p0[2], p0[3]);
                aPh[mb][2] = hipack(p1[0], p1[1]);
                aPh[mb][3] = hipack(p1[2], p1[3]);
                aPl[mb][0] = bf16pair(r00, r01);
                aPl[mb][1] = bf16pair(r02, r03);
                aPl[mb][2] = bf16pair(r10, r11);
                aPl[mb][3] = bf16pair(r12, r13);
            }
            #pragma unroll
            for (int nb = 0; nb < 4; nb++) {
                const uint32_t* vph = Vph + (tp0 + kt * 8 + t) * VS + nb * 8 + g;
                const uint32_t* vpl = Vpl + (tp0 + kt * 8 + t) * VS + nb * 8 + g;
                uint32_t vh[2], vl[2];
                vh[0] = vph[0]; vh[1] = vph[4 * VS];
                vl[0] = vpl[0]; vl[1] = vpl[4 * VS];
                #pragma unroll
                for (int mb = 0; mb < 2; mb++) {
                    mma_bf16(o[mb][nb], aPh[mb], vh);
                    mma_bf16(o[mb][nb], aPh[mb], vl);
                    mma_bf16(o[mb][nb], aPl[mb], vh);
                }
            }
        }
    }

    // ---- normalize, gate, store as packed hi/lo pair planes ----
    #pragma unroll
    for (int mb = 0; mb < 2; mb++) {
        float la = lsum[mb][0], lb = lsum[mb][1];
        la += __shfl_xor_sync(0xffffffffu, la, 1);
        la += __shfl_xor_sync(0xffffffffu, la, 2);
        lb += __shfl_xor_sync(0xffffffffu, lb, 1);
        lb += __shfl_xor_sync(0xffffffffu, lb, 2);
        float inv1 = 1.0f / la, inv2 = 1.0f / lb;
        int j1 = jb + mb * 16 + g, j2 = j1 + 8;
        #pragma unroll
        for (int nb = 0; nb < 4; nb++) {
            int d = nb * 8 + 2 * t;
            int pr = (coff >> 1) + nb * 4 + t;
            float2 g1 = *(const float2*)(g_g + (gbase + j1) * C + coff + d);
            float2 g2 = *(const float2*)(g_g + (gbase + j2) * C + coff + d);
            float o1x = g1.x * o[mb][nb][0] * inv1;
            float o1y = g1.y * o[mb][nb][1] * inv1;
            float o2x = g2.x * o[mb][nb][2] * inv2;
            float o2y = g2.y * o[mb][nb][3] * inv2;
            size_t p1 = (gbase + j1) * 64 + pr;
            size_t p2 = (gbase + j2) * 64 + pr;
            g_oh[p1] = hipack(o1x, o1y);
            g_ol[p1] = bf16pair(o1x - trunc_hi(o1x), o1y - trunc_hi(o1y));
            g_oh[p2] = hipack(o2x, o2y);
            g_ol[p2] = bf16pair(o2x - trunc_hi(o2x), o2y - trunc_hi(o2y));
        }
    }
}

extern "C" void kernel_launch(void* const* d_in, const int* in_sizes, int n_in,
                              void* d_out, int out_size) {
    const float* z     = (const float*)d_in[0];
    const float* gamma = (const float*)d_in[1];
    const float* beta  = (const float*)d_in[2];
    const float* Wq    = (const float*)d_in[3];
    const float* Wk    = (const float*)d_in[4];
    const float* Wv    = (const float*)d_in[5];
    const float* Wb    = (const float*)d_in[6];
    const float* Wg    = (const float*)d_in[7];
    const float* Wout  = (const float*)d_in[8];
    float* out = (float*)d_out;

    void *p_xh, *p_xl, *p_q, *p_k, *p_v, *p_g, *p_oh, *p_ol;
    cudaGetSymbolAddress(&p_xh, g_xh);
    cudaGetSymbolAddress(&p_xl, g_xl);
    cudaGetSymbolAddress(&p_q, g_q);
    cudaGetSymbolAddress(&p_k, g_k);
    cudaGetSymbolAddress(&p_v, g_v);
    cudaGetSymbolAddress(&p_g, g_g);
    cudaGetSymbolAddress(&p_oh, g_oh);
    cudaGetSymbolAddress(&p_ol, g_ol);

    cudaFuncSetAttribute(gemm_ps,
                         cudaFuncAttributeMaxDynamicSharedMemorySize, GEMM_SMEM);
    cudaFuncSetAttribute(attn_mma,
                         cudaFuncAttributeMaxDynamicSharedMemorySize, ATTN_SMEM);

    ln_kernel<<<NT / 8, 256>>>(z, gamma, beta, Wb);
    W5 ws; ws.w[0] = Wq; ws.w[1] = Wk; ws.w[2] = Wv; ws.w[3] = Wg; ws.w[4] = Wout;
    wprep_kernel<<<dim3(32, 5), 256>>>(ws);

    Y4 yq; yq.p[0] = (float*)p_q; yq.p[1] = (float*)p_k;
    yq.p[2] = (float*)p_v; yq.p[3] = (float*)p_g;
    gemm_ps<<<NT / 64, GT, GEMM_SMEM>>>((const uint32_t*)p_xh, (const uint32_t*)p_xl,
                                        0, 4, yq, 0x8);

    attn_mma<<<dim3(N, H), AT, ATTN_SMEM>>>();

    Y4 yo; yo.p[0] = out; yo.p[1] = yo.p[2] = yo.p[3] = nullptr;
    gemm_ps<<<NT / 64, GT, GEMM_SMEM>>>((const uint32_t*)p_oh, (const uint32_t*)p_ol,
                                        4, 1, yo, 0);
}